// round 11
// baseline (speedup 1.0000x reference)
#include <cuda_runtime.h>
#include <cuda_bf16.h>
#include <math.h>

#define Bz   2
#define Sq   2048
#define Hh   16
#define Dd   128
#define HID  2048
#define MM   (Bz*Sq)        // 4096

// ---------------- scratch (static device globals; no allocs) ----------------
// permuted packed hi/lo (GEMM operands; word groups [w0,w4,w1,w5,w2,w6,w3,w7])
__device__ __align__(16) unsigned g_hs_hi[MM*(HID/2)], g_hs_lo[MM*(HID/2)];
__device__ __align__(16) unsigned g_wq_hi[HID*(HID/2)], g_wq_lo[HID*(HID/2)];
__device__ __align__(16) unsigned g_wk_hi[Dd*(HID/2)], g_wk_lo[Dd*(HID/2)];
__device__ __align__(16) unsigned g_wv_hi[Dd*(HID/2)], g_wv_lo[Dd*(HID/2)];
__device__ __align__(16) unsigned g_wo_hi[HID*(HID/2)], g_wo_lo[HID*(HID/2)];
__device__ __align__(16) unsigned g_q_hi[MM*(HID/2)],  g_q_lo[MM*(HID/2)];
__device__ __align__(16) unsigned g_a_hi[MM*(HID/2)],  g_a_lo[MM*(HID/2)];
__device__ float    g_k[MM*Dd];   // fp32 K (cache broadcast)
__device__ float    g_v[MM*Dd];   // fp32 V (cache broadcast)
// INTERLEAVED hi/lo pair layout for attention operands:
// per original word w (bf16x2 pair): new index = 4*(w>>1) + 2*isLo + (w&1)
// -> one uint4 = (hi_pair(tig), hi_pair(tig+4), lo_pair(tig), lo_pair(tig+4))
__device__ __align__(16) unsigned g_k2[MM*128];          // K rows: 128 words interleaved
__device__ __align__(16) unsigned g_vT2[Dd*(MM/2)*2];    // V^T rows d: per 64-key block, 64 words interleaved

// ---------------------------------------------------------------------------
// helpers
// ---------------------------------------------------------------------------
__device__ __forceinline__ void split2(float x0, float x1, unsigned& hi, unsigned& lo)
{
    __nv_bfloat16 h0 = __float2bfloat16(x0);
    __nv_bfloat16 h1 = __float2bfloat16(x1);
    __nv_bfloat16 l0 = __float2bfloat16(x0 - __bfloat162float(h0));
    __nv_bfloat16 l1 = __float2bfloat16(x1 - __bfloat162float(h1));
    hi = ((unsigned)__bfloat16_as_ushort(h1) << 16) | (unsigned)__bfloat16_as_ushort(h0);
    lo = ((unsigned)__bfloat16_as_ushort(l1) << 16) | (unsigned)__bfloat16_as_ushort(l0);
}

__device__ __forceinline__ void mma_bf16(float c[4],
    unsigned a0, unsigned a1, unsigned a2, unsigned a3,
    unsigned b0, unsigned b1)
{
    asm volatile(
        "mma.sync.aligned.m16n8k16.row.col.f32.bf16.bf16.f32 "
        "{%0,%1,%2,%3}, {%4,%5,%6,%7}, {%8,%9}, {%0,%1,%2,%3};"
        : "+f"(c[0]), "+f"(c[1]), "+f"(c[2]), "+f"(c[3])
        : "r"(a0), "r"(a1), "r"(a2), "r"(a3), "r"(b0), "r"(b1));
}

__device__ __forceinline__ void cp16(unsigned dst, const void* src)
{
    asm volatile("cp.async.cg.shared.global [%0], [%1], 16;" :: "r"(dst), "l"(src));
}
__device__ __forceinline__ void cp_commit()
{
    asm volatile("cp.async.commit_group;");
}
template<int N>
__device__ __forceinline__ void cp_wait()
{
    asm volatile("cp.async.wait_group %0;" :: "n"(N));
}

__device__ __forceinline__ int permw(int w)
{
    int ww = w & 7;
    int slot = (ww < 4) ? (2 * ww) : (2 * ww - 7);
    return (w & ~7) | slot;
}

__device__ __forceinline__ unsigned smem_u32(const void* p)
{
    return (unsigned)__cvta_generic_to_shared(p);
}

// ---------------------------------------------------------------------------
// presplit: fp32 -> hi/lo packed words in permuted group order
// ---------------------------------------------------------------------------
__global__ __launch_bounds__(256)
void presplit(const float* __restrict__ X, unsigned* __restrict__ Hi,
              unsigned* __restrict__ Lo, int ngroups)
{
    int gi = blockIdx.x * 256 + threadIdx.x;
    if (gi >= ngroups) return;
    const float4* src = (const float4*)X + (size_t)gi * 4;
    unsigned wh[8], wl[8];
    #pragma unroll
    for (int i = 0; i < 4; i++) {
        float4 v = src[i];
        split2(v.x, v.y, wh[2*i],   wl[2*i]);
        split2(v.z, v.w, wh[2*i+1], wl[2*i+1]);
    }
    uint4 h0 = {wh[0], wh[4], wh[1], wh[5]};
    uint4 h1 = {wh[2], wh[6], wh[3], wh[7]};
    uint4 l0 = {wl[0], wl[4], wl[1], wl[5]};
    uint4 l1 = {wl[2], wl[6], wl[3], wl[7]};
    ((uint4*)Hi)[(size_t)gi*2]   = h0;  ((uint4*)Hi)[(size_t)gi*2+1] = h1;
    ((uint4*)Lo)[(size_t)gi*2]   = l0;  ((uint4*)Lo)[(size_t)gi*2+1] = l1;
}

// ---------------------------------------------------------------------------
// warp-mma 3xBF16 GEMM core (pre-split+permuted operands, cp.async 2-stage,
// LDS.64 fragment loads) — unchanged from the passing R6 kernel.
// ---------------------------------------------------------------------------
#define BM 128
#define BN 128
#define GWS 24
#define GST (BM*GWS)
#define GEMM_SMEM_BYTES (8*GST*4)

__device__ __forceinline__ void gemm_core2(
    const unsigned* __restrict__ Ahi, const unsigned* __restrict__ Alo,
    const unsigned* __restrict__ Bhi, const unsigned* __restrict__ Blo,
    int KW, int bm, int bn, unsigned* dsm, float acc[2][8][4])
{
    unsigned* sAh = dsm;
    unsigned* sAl = dsm + 2*GST;
    unsigned* sBh = dsm + 4*GST;
    unsigned* sBl = dsm + 6*GST;
    const unsigned sbase = smem_u32(dsm);

    const int t    = threadIdx.x;
    const int lane = t & 31, w = t >> 5;
    const int g    = lane >> 2, tig = lane & 3;
    const int wm   = w >> 1, wn = w & 1;

    #pragma unroll
    for (int i = 0; i < 2; i++)
        #pragma unroll
        for (int j = 0; j < 8; j++)
            #pragma unroll
            for (int q = 0; q < 4; q++) acc[i][j][q] = 0.f;

    const int cr = t >> 2, cc4 = (t & 3) * 4;
    auto issue = [&](int it, int bi) {
        const int kw0 = it * 16;
        unsigned dAh = sbase + (0*GST*2 + bi*GST) * 4;
        unsigned dAl = sbase + (1*GST*2 + bi*GST) * 4;
        unsigned dBh = sbase + (2*GST*2 + bi*GST) * 4;
        unsigned dBl = sbase + (3*GST*2 + bi*GST) * 4;
        #pragma unroll
        for (int i = 0; i < 2; i++) {
            int r = cr + 64 * i;
            size_t ao = (size_t)(bm + r) * KW + kw0 + cc4;
            size_t bo = (size_t)(bn + r) * KW + kw0 + cc4;
            unsigned so = (r * GWS + cc4) * 4;
            cp16(dAh + so, &Ahi[ao]);
            cp16(dAl + so, &Alo[ao]);
            cp16(dBh + so, &Bhi[bo]);
            cp16(dBl + so, &Blo[bo]);
        }
    };

    const int niter = KW / 16;
    issue(0, 0);
    cp_commit();

    for (int it = 0; it < niter; it++) {
        if (it + 1 < niter) { issue(it + 1, (it + 1) & 1); cp_commit(); cp_wait<1>(); }
        else                { cp_wait<0>(); }
        __syncthreads();

        const int bi = it & 1;
        const unsigned* pAh = sAh + bi * GST;
        const unsigned* pAl = sAl + bi * GST;
        const unsigned* pBh = sBh + bi * GST;
        const unsigned* pBl = sBl + bi * GST;

        #pragma unroll
        for (int ks = 0; ks < 2; ks++) {
            const int kb = ks * 8 + 2 * tig;
            uint2 ah0[2], ah1[2], al0[2], al1[2];
            #pragma unroll
            for (int mt = 0; mt < 2; mt++) {
                int m0r = wm * 32 + mt * 16;
                ah0[mt] = *(const uint2*)&pAh[(m0r + g    ) * GWS + kb];
                ah1[mt] = *(const uint2*)&pAh[(m0r + g + 8) * GWS + kb];
                al0[mt] = *(const uint2*)&pAl[(m0r + g    ) * GWS + kb];
                al1[mt] = *(const uint2*)&pAl[(m0r + g + 8) * GWS + kb];
            }
            #pragma unroll
            for (int nt = 0; nt < 8; nt++) {
                int nc = wn * 64 + nt * 8 + g;
                uint2 bhp = *(const uint2*)&pBh[nc * GWS + kb];
                uint2 blp = *(const uint2*)&pBl[nc * GWS + kb];
                #pragma unroll
                for (int mt = 0; mt < 2; mt++) {
                    mma_bf16(acc[mt][nt], ah0[mt].x, ah1[mt].x, ah0[mt].y, ah1[mt].y, blp.x, blp.y);
                    mma_bf16(acc[mt][nt], al0[mt].x, al1[mt].x, al0[mt].y, al1[mt].y, bhp.x, bhp.y);
                    mma_bf16(acc[mt][nt], ah0[mt].x, ah1[mt].x, ah0[mt].y, ah1[mt].y, bhp.x, bhp.y);
                }
            }
        }
        __syncthreads();
    }
}

// ---- Q projection: writes split+permuted g_q -------------------------------
__global__ __launch_bounds__(256, 2)
void gemm_q2(int M, int N, int K)
{
    extern __shared__ unsigned dsm[];
    float acc[2][8][4];
    const int bm = blockIdx.y * BM, bn = blockIdx.x * BN;
    gemm_core2(g_hs_hi, g_hs_lo, g_wq_hi, g_wq_lo, K >> 1, bm, bn, dsm, acc);

    const int t = threadIdx.x, lane = t & 31, w = t >> 5;
    const int g = lane >> 2, tig = lane & 3;
    const int wm = w >> 1, wn = w & 1;
    const int NW = N >> 1;
    #pragma unroll
    for (int mt = 0; mt < 2; mt++) {
        int r0 = bm + wm * 32 + mt * 16 + g;
        #pragma unroll
        for (int nt = 0; nt < 8; nt++) {
            int wp = permw((bn >> 1) + wn * 32 + nt * 4 + tig);
            unsigned h0, l0;
            split2(acc[mt][nt][0], acc[mt][nt][1], h0, l0);
            g_q_hi[(size_t)r0 * NW + wp] = h0;
            g_q_lo[(size_t)r0 * NW + wp] = l0;
            split2(acc[mt][nt][2], acc[mt][nt][3], h0, l0);
            g_q_hi[(size_t)(r0 + 8) * NW + wp] = h0;
            g_q_lo[(size_t)(r0 + 8) * NW + wp] = l0;
        }
    }
}

// ---- K + V projections (z=0 -> K, z=1 -> V); interleaved attn layouts ------
__global__ __launch_bounds__(256, 2)
void gemm_kv2(int M, int N, int K)
{
    extern __shared__ unsigned dsm[];
    float acc[2][8][4];
    const int bm = blockIdx.y * BM;
    const unsigned* Bh = blockIdx.z ? g_wv_hi : g_wk_hi;
    const unsigned* Bl = blockIdx.z ? g_wv_lo : g_wk_lo;
    gemm_core2(g_hs_hi, g_hs_lo, Bh, Bl, K >> 1, bm, 0, dsm, acc);

    const int t = threadIdx.x, lane = t & 31, w = t >> 5;
    const int g = lane >> 2, tig = lane & 3;
    const int wm = w >> 1, wn = w & 1;
    #pragma unroll
    for (int mt = 0; mt < 2; mt++) {
        int r0 = bm + wm * 32 + mt * 16 + g;
        #pragma unroll
        for (int nt = 0; nt < 8; nt++) {
            int c0 = wn * 64 + nt * 8 + tig * 2;
            float a0 = acc[mt][nt][0], a1 = acc[mt][nt][1];
            float a2 = acc[mt][nt][2], a3 = acc[mt][nt][3];
            if (blockIdx.z == 0) {
                *(float2*)&g_k[(size_t)r0 * N + c0]       = make_float2(a0, a1);
                *(float2*)&g_k[(size_t)(r0 + 8) * N + c0] = make_float2(a2, a3);
                int wp = permw(c0 >> 1);
                int nw = 4 * (wp >> 1) + (wp & 1);       // hi slot; lo = +2
                unsigned h0, l0;
                split2(a0, a1, h0, l0);
                g_k2[(size_t)r0 * 128 + nw]     = h0;
                g_k2[(size_t)r0 * 128 + nw + 2] = l0;
                split2(a2, a3, h0, l0);
                g_k2[(size_t)(r0 + 8) * 128 + nw]     = h0;
                g_k2[(size_t)(r0 + 8) * 128 + nw + 2] = l0;
            } else {
                *(float2*)&g_v[(size_t)r0 * N + c0]       = make_float2(a0, a1);
                *(float2*)&g_v[(size_t)(r0 + 8) * N + c0] = make_float2(a2, a3);
                __nv_bfloat16* vb = (__nv_bfloat16*)g_vT2;
                #pragma unroll
                for (int q = 0; q < 4; q++) {
                    float val = acc[mt][nt][q];
                    int cc = c0 + (q & 1);               // d index
                    int rr = r0 + (q >> 1) * 8;          // s index
                    int wloc = permw(rr >> 1) & 31;      // word within 64-key block
                    int kbt  = rr >> 6;                  // 64-key block index
                    int nw = 4 * (wloc >> 1) + (wloc & 1);   // hi slot; lo = +2
                    __nv_bfloat16 hh = __float2bfloat16(val);
                    __nv_bfloat16 ll = __float2bfloat16(val - __bfloat162float(hh));
                    size_t base = (size_t)cc * (MM * 2) + (size_t)kbt * 128 + nw * 2 + (rr & 1);
                    vb[base]     = hh;
                    vb[base + 4] = ll;                   // lo word = +2 words = +4 elems
                }
            }
        }
    }
}

// ---- O projection: fp32 output ---------------------------------------------
__global__ __launch_bounds__(256, 2)
void gemm_o2(float* __restrict__ C, int M, int N, int K)
{
    extern __shared__ unsigned dsm[];
    float acc[2][8][4];
    const int bm = blockIdx.y * BM, bn = blockIdx.x * BN;
    gemm_core2(g_a_hi, g_a_lo, g_wo_hi, g_wo_lo, K >> 1, bm, bn, dsm, acc);

    const int t = threadIdx.x, lane = t & 31, w = t >> 5;
    const int g = lane >> 2, tig = lane & 3;
    const int wm = w >> 1, wn = w & 1;
    #pragma unroll
    for (int mt = 0; mt < 2; mt++) {
        int r0 = bm + wm * 32 + mt * 16 + g;
        #pragma unroll
        for (int nt = 0; nt < 8; nt++) {
            int c0 = bn + wn * 64 + nt * 8 + tig * 2;
            *(float2*)&C[(size_t)r0 * N + c0]       = make_float2(acc[mt][nt][0], acc[mt][nt][1]);
            *(float2*)&C[(size_t)(r0 + 8) * N + c0] = make_float2(acc[mt][nt][2], acc[mt][nt][3]);
        }
    }
}

// ---------------------------------------------------------------------------
// FlashAttention-2, interleaved hi/lo smem -> LDS.128 fragment loads.
// K rows: 128 data words + 16 pad = 144 (144%32==16 -> CF LDS.128 phases)
// V rows:  64 data words + 16 pad =  80 ( 80%32==16 -> CF)
// ---------------------------------------------------------------------------
#define KROW 144
#define VROW 80
#define KBUF (64*KROW)     // 9216 words per stage
#define VBUF (128*VROW)    // 10240 words per stage
#define ATTN_SMEM_WORDS (2*KBUF + 2*VBUF + Sq)   // 40960
#define NT_TILES (Sq/64)

__global__ __launch_bounds__(256, 1)
void attn_kernel(const float* __restrict__ mask)
{
    extern __shared__ unsigned smw[];
    // K stages at [0, 2*KBUF); V stages at [2*KBUF, 2*KBUF+2*VBUF); mask after
    float* maskrow = (float*)(smw + 2*KBUF + 2*VBUF);

    const unsigned sbase = smem_u32(smw);

    const int t    = threadIdx.x;
    const int lane = t & 31, w = t >> 5;
    const int g    = lane >> 2, tig = lane & 3;
    const int qt   = blockIdx.x;
    const int bh   = blockIdx.y;
    const int b    = bh / Hh;
    const int h    = bh % Hh;
    const int m0   = w * 16;

    const float scale = 0.08838834764831845f;
    const float NEG   = -3.402823466e38f;

    // ---- stage mask row with premultiplied mterm ----
    #pragma unroll
    for (int i = 0; i < 2; i++) {
        int c = t + 256 * i;
        float4 m4 = *(const float4*)&mask[b * Sq + c * 4];
        m4.x = (1.0f - m4.x) * NEG;
        m4.y = (1.0f - m4.y) * NEG;
        m4.z = (1.0f - m4.z) * NEG;
        m4.w = (1.0f - m4.w) * NEG;
        *(float4*)&maskrow[c * 4] = m4;
    }

    // ---- stage Q (128 rows) into K stage area: hi words +0..63, lo +64..127
    #pragma unroll
    for (int i = 0; i < 8; i++) {
        int c = t + 256 * i;               // 2048 chunks
        int r = c >> 4, cw = (c & 15) * 4;
        size_t goff = (size_t)(b * Sq + qt * 128 + r) * (HID/2) + h * (Dd/2) + cw;
        *(uint4*)&smw[r * KROW + cw]      = *(const uint4*)&g_q_hi[goff];
        *(uint4*)&smw[r * KROW + 64 + cw] = *(const uint4*)&g_q_lo[goff];
    }
    __syncthreads();

    unsigned qh[8][4], ql[8][4];
    #pragma unroll
    for (int kf = 0; kf < 8; kf++) {
        int kb = kf * 8 + 2 * tig;
        uint2 p0 = *(const uint2*)&smw[(m0 + g    ) * KROW + kb];
        uint2 p1 = *(const uint2*)&smw[(m0 + g + 8) * KROW + kb];
        qh[kf][0] = p0.x; qh[kf][1] = p1.x; qh[kf][2] = p0.y; qh[kf][3] = p1.y;
        p0 = *(const uint2*)&smw[(m0 + g    ) * KROW + 64 + kb];
        p1 = *(const uint2*)&smw[(m0 + g + 8) * KROW + 64 + kb];
        ql[kf][0] = p0.x; ql[kf][1] = p1.x; ql[kf][2] = p0.y; ql[kf][3] = p1.y;
    }
    __syncthreads();

    float o[16][4];
    #pragma unroll
    for (int nd = 0; nd < 16; nd++)
        #pragma unroll
        for (int q = 0; q < 4; q++) o[nd][q] = 0.f;
    float mrow0 = -INFINITY, mrow1 = -INFINITY;
    float lsum0 = 0.f, lsum1 = 0.f;

    auto issue = [&](int kt, int bi) {
        unsigned dK = sbase + (bi * KBUF) * 4;
        unsigned dV = sbase + (2*KBUF + bi * VBUF) * 4;
        // K: 64 rows x 32 chunks of 16B
        #pragma unroll
        for (int i = 0; i < 8; i++) {
            int c = t + 256 * i;               // 0..2047
            int r = c >> 5, cc = (c & 31) * 4; // word col
            size_t goff = (size_t)(b * Sq + kt * 64 + r) * 128 + cc;
            cp16(dK + (r * KROW + cc) * 4, &g_k2[goff]);
        }
        // V: 128 rows x 16 chunks of 16B
        #pragma unroll
        for (int i = 0; i < 8; i++) {
            int c = t + 256 * i;               // 0..2047
            int r = c >> 4, cc = (c & 15) * 4;
            size_t goff = (size_t)r * (MM) + (size_t)(b * 32 + kt) * 64 + cc;
            cp16(dV + (r * VROW + cc) * 4, &g_vT2[goff]);
        }
    };

    issue(0, 0);
    cp_commit();

    for (int kt = 0; kt < NT_TILES; kt++) {
        const int bi = kt & 1;
        if (kt + 1 < NT_TILES) { issue(kt + 1, bi ^ 1); cp_commit(); cp_wait<1>(); }
        else                   { cp_wait<0>(); }
        __syncthreads();

        const unsigned* Kb = smw + bi * KBUF;
        const unsigned* Vb = smw + 2*KBUF + bi * VBUF;

        // ----- QK^T : LDS.128 fragment loads
        float s[8][4];
        #pragma unroll
        for (int nt = 0; nt < 8; nt++)
            #pragma unroll
            for (int q = 0; q < 4; q++) s[nt][q] = 0.f;

        #pragma unroll
        for (int kf = 0; kf < 8; kf++) {
            const int kb = kf * 16 + 4 * tig;
            #pragma unroll
            for (int nt = 0; nt < 8; nt++) {
                int nc = nt * 8 + g;
                uint4 f = *(const uint4*)&Kb[nc * KROW + kb];
                mma_bf16(s[nt], qh[kf][0], qh[kf][1], qh[kf][2], qh[kf][3], f.z, f.w);
                mma_bf16(s[nt], ql[kf][0], ql[kf][1], ql[kf][2], ql[kf][3], f.x, f.y);
                mma_bf16(s[nt], qh[kf][0], qh[kf][1], qh[kf][2], qh[kf][3], f.x, f.y);
            }
        }

        // ----- scale + mask + register softmax
        float m0new = -INFINITY, m1new = -INFINITY;
        #pragma unroll
        for (int nt = 0; nt < 8; nt++) {
            int c0 = kt * 64 + nt * 8 + tig * 2;
            float mt0 = maskrow[c0];
            float mt1 = maskrow[c0 + 1];
            s[nt][0] = s[nt][0] * scale + mt0;
            s[nt][1] = s[nt][1] * scale + mt1;
            s[nt][2] = s[nt][2] * scale + mt0;
            s[nt][3] = s[nt][3] * scale + mt1;
            m0new = fmaxf(m0new, fmaxf(s[nt][0], s[nt][1]));
            m1new = fmaxf(m1new, fmaxf(s[nt][2], s[nt][3]));
        }
        m0new = fmaxf(m0new, __shfl_xor_sync(0xffffffffu, m0new, 1));
        m0new = fmaxf(m0new, __shfl_xor_sync(0xffffffffu, m0new, 2));
        m1new = fmaxf(m1new, __shfl_xor_sync(0xffffffffu, m1new, 1));
        m1new = fmaxf(m1new, __shfl_xor_sync(0xffffffffu, m1new, 2));

        float newm0 = fmaxf(mrow0, m0new);
        float newm1 = fmaxf(mrow1, m1new);
        float corr0 = __expf(mrow0 - newm0);
        float corr1 = __expf(mrow1 - newm1);
        mrow0 = newm0; mrow1 = newm1;

        float ps0 = 0.f, ps1 = 0.f;
        #pragma unroll
        for (int nt = 0; nt < 8; nt++) {
            s[nt][0] = __expf(s[nt][0] - newm0);
            s[nt][1] = __expf(s[nt][1] - newm0);
            s[nt][2] = __expf(s[nt][2] - newm1);
            s[nt][3] = __expf(s[nt][3] - newm1);
            ps0 += s[nt][0] + s[nt][1];
            ps1 += s[nt][2] + s[nt][3];
        }
        ps0 += __shfl_xor_sync(0xffffffffu, ps0, 1);
        ps0 += __shfl_xor_sync(0xffffffffu, ps0, 2);
        ps1 += __shfl_xor_sync(0xffffffffu, ps1, 1);
        ps1 += __shfl_xor_sync(0xffffffffu, ps1, 2);
        lsum0 = lsum0 * corr0 + ps0;
        lsum1 = lsum1 * corr1 + ps1;

        #pragma unroll
        for (int nd = 0; nd < 16; nd++) {
            o[nd][0] *= corr0; o[nd][1] *= corr0;
            o[nd][2] *= corr1; o[nd][3] *= corr1;
        }

        // ----- PV : LDS.128 fragment loads
        #pragma unroll
        for (int kf = 0; kf < 4; kf++) {
            unsigned a0h, a0l, a1h, a1l, a2h, a2l, a3h, a3l;
            split2(s[2*kf  ][0], s[2*kf  ][1], a0h, a0l);
            split2(s[2*kf  ][2], s[2*kf  ][3], a1h, a1l);
            split2(s[2*kf+1][0], s[2*kf+1][1], a2h, a2l);
            split2(s[2*kf+1][2], s[2*kf+1][3], a3h, a3l);
            const int kb = kf * 16 + 4 * tig;
            #pragma unroll
            for (int nd = 0; nd < 16; nd++) {
                int nc = nd * 8 + g;
                uint4 f = *(const uint4*)&Vb[nc * VROW + kb];
                mma_bf16(o[nd], a0h, a1h, a2h, a3h, f.z, f.w);
                mma_bf16(o[nd], a0l, a1l, a2l, a3l, f.x, f.y);
                mma_bf16(o[nd], a0h, a1h, a2h, a3h, f.x, f.y);
            }
        }
        __syncthreads();
    }

    // ---- epilogue: normalize, split, plain packed write (natural order) ----
    float inv0 = 1.0f / lsum0;
    float inv1 = 1.0f / lsum1;
    size_t row0 = (size_t)(b * Sq + qt * 128 + m0 + g);
    #pragma unroll
    for (int nd = 0; nd < 16; nd++) {
        int cw = permw(h * (Dd/2) + nd * 4 + tig);
        unsigned hh, llw;
        split2(o[nd][0] * inv0, o[nd][1] * inv0, hh, llw);
        g_a_hi[row0 * (HID/2) + cw] = hh;
        g_a_lo[row0 * (HID/2) + cw] = llw;
        split2(o[nd][2] * inv1, o[nd][3] * inv1, hh, llw);
        g_a_hi[(row0 + 8) * (HID/2) + cw] = hh;
        g_a_lo[(row0 + 8) * (HID/2) + cw] = llw;
    }
}

// ---------------------------------------------------------------------------
// KV cache broadcast
// ---------------------------------------------------------------------------
__global__ __launch_bounds__(256)
void kv_broadcast(float* __restrict__ out)
{
    int i = blockIdx.x * 256 + threadIdx.x;
    int o = i * 4;
    int b = o / (Sq * Dd);
    int rem = o - b * Sq * Dd;
    int s = rem / Dd;
    int d = rem - s * Dd;
    float4 kv = *(const float4*)&g_k[o];
    float4 vv = *(const float4*)&g_v[o];
    const size_t keybase = (size_t)MM * HID;
    const size_t valbase = keybase + (size_t)Bz * Hh * Sq * Dd;
    #pragma unroll
    for (int h = 0; h < Hh; h++) {
        size_t idx = (((size_t)b * Hh + h) * Sq + s) * Dd + d;
        *(float4*)&out[keybase + idx] = kv;
        *(float4*)&out[valbase + idx] = vv;
    }
}

// ---------------------------------------------------------------------------
extern "C" void kernel_launch(void* const* d_in, const int* in_sizes, int n_in,
                              void* d_out, int out_size)
{
    const float* hs   = (const float*)d_in[0];
    const float* mask = (const float*)d_in[1];
    const float* Wq   = (const float*)d_in[2];
    const float* Wk   = (const float*)d_in[3];
    const float* Wv   = (const float*)d_in[4];
    const float* Wo   = (const float*)d_in[5];
    float* out = (float*)d_out;

    void *hsh, *hsl, *wqh, *wql, *wkh, *wkl, *wvh, *wvl, *woh, *wol;
    cudaGetSymbolAddress(&hsh, g_hs_hi);  cudaGetSymbolAddress(&hsl, g_hs_lo);
    cudaGetSymbolAddress(&wqh, g_wq_hi);  cudaGetSymbolAddress(&wql, g_wq_lo);
    cudaGetSymbolAddress(&wkh, g_wk_hi);  cudaGetSymbolAddress(&wkl, g_wk_lo);
    cudaGetSymbolAddress(&wvh, g_wv_hi);  cudaGetSymbolAddress(&wvl, g_wv_lo);
    cudaGetSymbolAddress(&woh, g_wo_hi);  cudaGetSymbolAddress(&wol, g_wo_lo);

    cudaFuncSetAttribute(attn_kernel, cudaFuncAttributeMaxDynamicSharedMemorySize,
                         ATTN_SMEM_WORDS * 4);
    cudaFuncSetAttribute(gemm_q2,  cudaFuncAttributeMaxDynamicSharedMemorySize, GEMM_SMEM_BYTES);
    cudaFuncSetAttribute(gemm_kv2, cudaFuncAttributeMaxDynamicSharedMemorySize, GEMM_SMEM_BYTES);
    cudaFuncSetAttribute(gemm_o2,  cudaFuncAttributeMaxDynamicSharedMemorySize, GEMM_SMEM_BYTES);

    dim3 blk(256);
    // presplit inputs (permuted hi/lo word layout)
    presplit<<<MM*HID/16/256,  blk>>>(hs, (unsigned*)hsh, (unsigned*)hsl, MM*HID/16);
    presplit<<<HID*HID/16/256, blk>>>(Wq, (unsigned*)wqh, (unsigned*)wql, HID*HID/16);
    presplit<<<Dd*HID/16/256,  blk>>>(Wk, (unsigned*)wkh, (unsigned*)wkl, Dd*HID/16);
    presplit<<<Dd*HID/16/256,  blk>>>(Wv, (unsigned*)wvh, (unsigned*)wvl, Dd*HID/16);
    presplit<<<HID*HID/16/256, blk>>>(Wo, (unsigned*)woh, (unsigned*)wol, HID*HID/16);

    // projections
    gemm_q2 <<<dim3(HID / BN, MM / BM),    blk, GEMM_SMEM_BYTES>>>(MM, HID, HID);
    gemm_kv2<<<dim3(1, MM / BM, 2),        blk, GEMM_SMEM_BYTES>>>(MM, Dd, HID);
    // KV cache broadcast
    kv_broadcast<<<(MM * Dd / 4 + 255) / 256, blk>>>(out);
    // attention
    attn_kernel<<<dim3(Sq / 128, Bz * Hh), blk, ATTN_SMEM_WORDS * 4>>>(mask);
    // output projection
    gemm_o2 <<<dim3(HID / BN, MM / BM),    blk, GEMM_SMEM_BYTES>>>(out, MM, HID, HID);
}

// round 12
// speedup vs baseline: 1.0864x; 1.0864x over previous
#include <cuda_runtime.h>
#include <cuda_bf16.h>
#include <math.h>

#define Bz   2
#define Sq   2048
#define Hh   16
#define Dd   128
#define HID  2048
#define MM   (Bz*Sq)        // 4096

// ---------------- scratch (static device globals; no allocs) ----------------
// permuted packed hi/lo word layout: groups of 8 words stored [w0,w4,w1,w5,w2,w6,w3,w7]
__device__ __align__(16) unsigned g_hs_hi[MM*(HID/2)], g_hs_lo[MM*(HID/2)];
__device__ __align__(16) unsigned g_wq_hi[HID*(HID/2)], g_wq_lo[HID*(HID/2)];
__device__ __align__(16) unsigned g_wk_hi[Dd*(HID/2)], g_wk_lo[Dd*(HID/2)];
__device__ __align__(16) unsigned g_wv_hi[Dd*(HID/2)], g_wv_lo[Dd*(HID/2)];
__device__ __align__(16) unsigned g_wo_hi[HID*(HID/2)], g_wo_lo[HID*(HID/2)];
__device__ __align__(16) unsigned g_q_hi[MM*(HID/2)],  g_q_lo[MM*(HID/2)];
__device__ __align__(16) unsigned g_k_hi[MM*(Dd/2)],   g_k_lo[MM*(Dd/2)];
__device__ __align__(16) __nv_bfloat16 g_vT_hi[Dd*MM], g_vT_lo[Dd*MM];
__device__ __align__(16) unsigned g_a_hi[MM*(HID/2)],  g_a_lo[MM*(HID/2)];

// ---------------------------------------------------------------------------
// helpers
// ---------------------------------------------------------------------------
__device__ __forceinline__ void split2(float x0, float x1, unsigned& hi, unsigned& lo)
{
    __nv_bfloat16 h0 = __float2bfloat16(x0);
    __nv_bfloat16 h1 = __float2bfloat16(x1);
    __nv_bfloat16 l0 = __float2bfloat16(x0 - __bfloat162float(h0));
    __nv_bfloat16 l1 = __float2bfloat16(x1 - __bfloat162float(h1));
    hi = ((unsigned)__bfloat16_as_ushort(h1) << 16) | (unsigned)__bfloat16_as_ushort(h0);
    lo = ((unsigned)__bfloat16_as_ushort(l1) << 16) | (unsigned)__bfloat16_as_ushort(l0);
}

__device__ __forceinline__ void mma_bf16(float c[4],
    unsigned a0, unsigned a1, unsigned a2, unsigned a3,
    unsigned b0, unsigned b1)
{
    asm volatile(
        "mma.sync.aligned.m16n8k16.row.col.f32.bf16.bf16.f32 "
        "{%0,%1,%2,%3}, {%4,%5,%6,%7}, {%8,%9}, {%0,%1,%2,%3};"
        : "+f"(c[0]), "+f"(c[1]), "+f"(c[2]), "+f"(c[3])
        : "r"(a0), "r"(a1), "r"(a2), "r"(a3), "r"(b0), "r"(b1));
}

__device__ __forceinline__ void cp16(unsigned dst, const void* src)
{
    asm volatile("cp.async.cg.shared.global [%0], [%1], 16;" :: "r"(dst), "l"(src));
}
__device__ __forceinline__ void cp_commit()
{
    asm volatile("cp.async.commit_group;");
}
template<int N>
__device__ __forceinline__ void cp_wait()
{
    asm volatile("cp.async.wait_group %0;" :: "n"(N));
}

__device__ __forceinline__ int permw(int w)
{
    int ww = w & 7;
    int slot = (ww < 4) ? (2 * ww) : (2 * ww - 7);
    return (w & ~7) | slot;
}

__device__ __forceinline__ unsigned smem_u32(const void* p)
{
    return (unsigned)__cvta_generic_to_shared(p);
}

// ---------------------------------------------------------------------------
// presplit: fp32 -> hi/lo packed words in permuted group order
// ---------------------------------------------------------------------------
__device__ __forceinline__ void presplit_one(const float* __restrict__ X,
    unsigned* __restrict__ Hi, unsigned* __restrict__ Lo, int gi)
{
    const float4* src = (const float4*)X + (size_t)gi * 4;
    unsigned wh[8], wl[8];
    #pragma unroll
    for (int i = 0; i < 4; i++) {
        float4 v = src[i];
        split2(v.x, v.y, wh[2*i],   wl[2*i]);
        split2(v.z, v.w, wh[2*i+1], wl[2*i+1]);
    }
    uint4 h0 = {wh[0], wh[4], wh[1], wh[5]};
    uint4 h1 = {wh[2], wh[6], wh[3], wh[7]};
    uint4 l0 = {wl[0], wl[4], wl[1], wl[5]};
    uint4 l1 = {wl[2], wl[6], wl[3], wl[7]};
    ((uint4*)Hi)[(size_t)gi*2]   = h0;  ((uint4*)Hi)[(size_t)gi*2+1] = h1;
    ((uint4*)Lo)[(size_t)gi*2]   = l0;  ((uint4*)Lo)[(size_t)gi*2+1] = l1;
}

__global__ __launch_bounds__(256)
void presplit(const float* __restrict__ X, unsigned* __restrict__ Hi,
              unsigned* __restrict__ Lo, int ngroups)
{
    int gi = blockIdx.x * 256 + threadIdx.x;
    if (gi >= ngroups) return;
    presplit_one(X, Hi, Lo, gi);
}

// merged Wk+Wv presplit (z: 0 -> Wk, 1 -> Wv)
__global__ __launch_bounds__(256)
void presplit_kv(const float* __restrict__ Wk, const float* __restrict__ Wv,
                 int ngroups)
{
    int gi = blockIdx.x * 256 + threadIdx.x;
    if (gi >= ngroups) return;
    if (blockIdx.y == 0) presplit_one(Wk, g_wk_hi, g_wk_lo, gi);
    else                 presplit_one(Wv, g_wv_hi, g_wv_lo, gi);
}

// ---------------------------------------------------------------------------
// warp-mma 3xBF16 GEMM core (pre-split+permuted operands, cp.async 2-stage,
// LDS.64 fragment loads) — identical to the R6-passing kernel.
// ---------------------------------------------------------------------------
#define BM 128
#define BN 128
#define GWS 24
#define GST (BM*GWS)
#define GEMM_SMEM_BYTES (8*GST*4)

__device__ __forceinline__ void gemm_core2(
    const unsigned* __restrict__ Ahi, const unsigned* __restrict__ Alo,
    const unsigned* __restrict__ Bhi, const unsigned* __restrict__ Blo,
    int KW, int bm, int bn, unsigned* dsm, float acc[2][8][4])
{
    unsigned* sAh = dsm;
    unsigned* sAl = dsm + 2*GST;
    unsigned* sBh = dsm + 4*GST;
    unsigned* sBl = dsm + 6*GST;
    const unsigned sbase = smem_u32(dsm);

    const int t    = threadIdx.x;
    const int lane = t & 31, w = t >> 5;
    const int g    = lane >> 2, tig = lane & 3;
    const int wm   = w >> 1, wn = w & 1;

    #pragma unroll
    for (int i = 0; i < 2; i++)
        #pragma unroll
        for (int j = 0; j < 8; j++)
            #pragma unroll
            for (int q = 0; q < 4; q++) acc[i][j][q] = 0.f;

    const int cr = t >> 2, cc4 = (t & 3) * 4;
    auto issue = [&](int it, int bi) {
        const int kw0 = it * 16;
        unsigned dAh = sbase + (0*GST*2 + bi*GST) * 4;
        unsigned dAl = sbase + (1*GST*2 + bi*GST) * 4;
        unsigned dBh = sbase + (2*GST*2 + bi*GST) * 4;
        unsigned dBl = sbase + (3*GST*2 + bi*GST) * 4;
        #pragma unroll
        for (int i = 0; i < 2; i++) {
            int r = cr + 64 * i;
            size_t ao = (size_t)(bm + r) * KW + kw0 + cc4;
            size_t bo = (size_t)(bn + r) * KW + kw0 + cc4;
            unsigned so = (r * GWS + cc4) * 4;
            cp16(dAh + so, &Ahi[ao]);
            cp16(dAl + so, &Alo[ao]);
            cp16(dBh + so, &Bhi[bo]);
            cp16(dBl + so, &Blo[bo]);
        }
    };

    const int niter = KW / 16;
    issue(0, 0);
    cp_commit();

    for (int it = 0; it < niter; it++) {
        if (it + 1 < niter) { issue(it + 1, (it + 1) & 1); cp_commit(); cp_wait<1>(); }
        else                { cp_wait<0>(); }
        __syncthreads();

        const int bi = it & 1;
        const unsigned* pAh = sAh + bi * GST;
        const unsigned* pAl = sAl + bi * GST;
        const unsigned* pBh = sBh + bi * GST;
        const unsigned* pBl = sBl + bi * GST;

        #pragma unroll
        for (int ks = 0; ks < 2; ks++) {
            const int kb = ks * 8 + 2 * tig;
            uint2 ah0[2], ah1[2], al0[2], al1[2];
            #pragma unroll
            for (int mt = 0; mt < 2; mt++) {
                int m0r = wm * 32 + mt * 16;
                ah0[mt] = *(const uint2*)&pAh[(m0r + g    ) * GWS + kb];
                ah1[mt] = *(const uint2*)&pAh[(m0r + g + 8) * GWS + kb];
                al0[mt] = *(const uint2*)&pAl[(m0r + g    ) * GWS + kb];
                al1[mt] = *(const uint2*)&pAl[(m0r + g + 8) * GWS + kb];
            }
            #pragma unroll
            for (int nt = 0; nt < 8; nt++) {
                int nc = wn * 64 + nt * 8 + g;
                uint2 bhp = *(const uint2*)&pBh[nc * GWS + kb];
                uint2 blp = *(const uint2*)&pBl[nc * GWS + kb];
                #pragma unroll
                for (int mt = 0; mt < 2; mt++) {
                    mma_bf16(acc[mt][nt], ah0[mt].x, ah1[mt].x, ah0[mt].y, ah1[mt].y, blp.x, blp.y);
                    mma_bf16(acc[mt][nt], al0[mt].x, al1[mt].x, al0[mt].y, al1[mt].y, bhp.x, bhp.y);
                    mma_bf16(acc[mt][nt], ah0[mt].x, ah1[mt].x, ah0[mt].y, ah1[mt].y, bhp.x, bhp.y);
                }
            }
        }
        __syncthreads();
    }
}

// ---------------------------------------------------------------------------
// merged Q/K/V projection: grid (18, 32). x<16: Q tile; x==16: K; x==17: V.
// K/V epilogues also write the 16-head-replicated cache outputs directly.
// ---------------------------------------------------------------------------
__global__ __launch_bounds__(256, 2)
void gemm_qkv(float* __restrict__ out, int M, int K)
{
    extern __shared__ unsigned dsm[];
    float acc[2][8][4];
    const int bm = blockIdx.y * BM;
    const int bx = blockIdx.x;

    const unsigned *Bhp, *Blp;
    int bn;
    if (bx < 16)      { Bhp = g_wq_hi; Blp = g_wq_lo; bn = bx * BN; }
    else if (bx == 16){ Bhp = g_wk_hi; Blp = g_wk_lo; bn = 0; }
    else              { Bhp = g_wv_hi; Blp = g_wv_lo; bn = 0; }

    gemm_core2(g_hs_hi, g_hs_lo, Bhp, Blp, K >> 1, bm, bn, dsm, acc);

    const int t = threadIdx.x, lane = t & 31, w = t >> 5;
    const int g = lane >> 2, tig = lane & 3;
    const int wm = w >> 1, wn = w & 1;

    if (bx < 16) {
        // ---- Q epilogue: split + permuted packed ----
        const int NW = HID >> 1;
        #pragma unroll
        for (int mt = 0; mt < 2; mt++) {
            int r0 = bm + wm * 32 + mt * 16 + g;
            #pragma unroll
            for (int nt = 0; nt < 8; nt++) {
                int wp = permw((bn >> 1) + wn * 32 + nt * 4 + tig);
                unsigned h0, l0;
                split2(acc[mt][nt][0], acc[mt][nt][1], h0, l0);
                g_q_hi[(size_t)r0 * NW + wp] = h0;
                g_q_lo[(size_t)r0 * NW + wp] = l0;
                split2(acc[mt][nt][2], acc[mt][nt][3], h0, l0);
                g_q_hi[(size_t)(r0 + 8) * NW + wp] = h0;
                g_q_lo[(size_t)(r0 + 8) * NW + wp] = l0;
            }
        }
        return;
    }

    // ---- K / V epilogues ----
    const int N  = Dd;
    const int NW = Dd >> 1;
    const size_t keybase = (size_t)MM * HID;                       // 8388608
    const size_t valbase = keybase + (size_t)Bz * Hh * Sq * Dd;    // 16777216
    const size_t cachebase = (bx == 16) ? keybase : valbase;

    #pragma unroll
    for (int mt = 0; mt < 2; mt++) {
        int r0 = bm + wm * 32 + mt * 16 + g;
        #pragma unroll
        for (int nt = 0; nt < 8; nt++) {
            int c0 = wn * 64 + nt * 8 + tig * 2;
            float a0 = acc[mt][nt][0], a1 = acc[mt][nt][1];
            float a2 = acc[mt][nt][2], a3 = acc[mt][nt][3];

            // 16-head replicated cache output (both rows r0 and r0+8)
            #pragma unroll
            for (int rr = 0; rr < 2; rr++) {
                int r = r0 + rr * 8;
                int b = r >> 11;            // /Sq
                int s = r & (Sq - 1);
                float2 v2 = rr ? make_float2(a2, a3) : make_float2(a0, a1);
                size_t base = cachebase + ((size_t)b * Hh * Sq + s) * Dd + c0;
                #pragma unroll
                for (int h = 0; h < Hh; h++)
                    *(float2*)&out[base + (size_t)h * Sq * Dd] = v2;
            }

            if (bx == 16) {
                // K: split + permuted packed for attention
                int wp = permw(c0 >> 1);
                unsigned h0, l0;
                split2(a0, a1, h0, l0);
                g_k_hi[(size_t)r0 * NW + wp] = h0;
                g_k_lo[(size_t)r0 * NW + wp] = l0;
                split2(a2, a3, h0, l0);
                g_k_hi[(size_t)(r0 + 8) * NW + wp] = h0;
                g_k_lo[(size_t)(r0 + 8) * NW + wp] = l0;
            } else {
                // V: transposed split bf16 with permuted s-position
                #pragma unroll
                for (int q = 0; q < 4; q++) {
                    float val = acc[mt][nt][q];
                    int cc = c0 + (q & 1);
                    int rr = r0 + (q >> 1) * 8;
                    int sp = permw(rr >> 1) * 2 + (rr & 1);
                    __nv_bfloat16 hh = __float2bfloat16(val);
                    __nv_bfloat16 ll = __float2bfloat16(val - __bfloat162float(hh));
                    g_vT_hi[(size_t)cc * MM + sp] = hh;
                    g_vT_lo[(size_t)cc * MM + sp] = ll;
                }
            }
        }
    }
}

// ---- O projection: fp32 output ---------------------------------------------
__global__ __launch_bounds__(256, 2)
void gemm_o2(float* __restrict__ C, int M, int N, int K)
{
    extern __shared__ unsigned dsm[];
    float acc[2][8][4];
    const int bm = blockIdx.y * BM, bn = blockIdx.x * BN;
    gemm_core2(g_a_hi, g_a_lo, g_wo_hi, g_wo_lo, K >> 1, bm, bn, dsm, acc);

    const int t = threadIdx.x, lane = t & 31, w = t >> 5;
    const int g = lane >> 2, tig = lane & 3;
    const int wm = w >> 1, wn = w & 1;
    #pragma unroll
    for (int mt = 0; mt < 2; mt++) {
        int r0 = bm + wm * 32 + mt * 16 + g;
        #pragma unroll
        for (int nt = 0; nt < 8; nt++) {
            int c0 = bn + wn * 64 + nt * 8 + tig * 2;
            *(float2*)&C[(size_t)r0 * N + c0]       = make_float2(acc[mt][nt][0], acc[mt][nt][1]);
            *(float2*)&C[(size_t)(r0 + 8) * N + c0] = make_float2(acc[mt][nt][2], acc[mt][nt][3]);
        }
    }
}

// ---------------------------------------------------------------------------
// FlashAttention-2 (R6-proven): 128 q rows/block, warp owns 16 rows, register
// softmax, cp.async double-buffered K/V, LDS.64 frag loads on permuted layout.
// ---------------------------------------------------------------------------
#define KROW 72
#define VROW 40
#define KBUF (64*KROW)
#define VBUF (128*VROW)
#define ATTN_SMEM_WORDS (4*KBUF + 4*VBUF + Sq)
#define NT_TILES (Sq/64)

__global__ __launch_bounds__(256, 1)
void attn_kernel(const float* __restrict__ mask)
{
    extern __shared__ unsigned smw[];
    unsigned* Kh0 = smw;
    unsigned* Kl0 = smw + 2*KBUF;
    unsigned* Vh0 = smw + 4*KBUF;
    unsigned* Vl0 = smw + 4*KBUF + 2*VBUF;
    float*  maskrow = (float*)(smw + 4*KBUF + 4*VBUF);

    const unsigned sbase = smem_u32(smw);

    const int t    = threadIdx.x;
    const int lane = t & 31, w = t >> 5;
    const int g    = lane >> 2, tig = lane & 3;
    const int qt   = blockIdx.x;
    const int bh   = blockIdx.y;
    const int b    = bh / Hh;
    const int h    = bh % Hh;
    const int m0   = w * 16;

    const float scale = 0.08838834764831845f;
    const float NEG   = -3.402823466e38f;

    #pragma unroll
    for (int i = 0; i < 2; i++) {
        int c = t + 256 * i;
        *(float4*)&maskrow[c * 4] = *(const float4*)&mask[b * Sq + c * 4];
    }

    #pragma unroll
    for (int i = 0; i < 8; i++) {
        int c = t + 256 * i;
        int r = c >> 4, cw = (c & 15) * 4;
        size_t goff = (size_t)(b * Sq + qt * 128 + r) * (HID/2) + h * (Dd/2) + cw;
        *(uint4*)&Kh0[r * KROW + cw] = *(const uint4*)&g_q_hi[goff];
        *(uint4*)&Kl0[r * KROW + cw] = *(const uint4*)&g_q_lo[goff];
    }
    __syncthreads();

    unsigned qh[8][4], ql[8][4];
    #pragma unroll
    for (int kf = 0; kf < 8; kf++) {
        int kb = kf * 8 + 2 * tig;
        uint2 p0 = *(const uint2*)&Kh0[(m0 + g    ) * KROW + kb];
        uint2 p1 = *(const uint2*)&Kh0[(m0 + g + 8) * KROW + kb];
        qh[kf][0] = p0.x; qh[kf][1] = p1.x; qh[kf][2] = p0.y; qh[kf][3] = p1.y;
        p0 = *(const uint2*)&Kl0[(m0 + g    ) * KROW + kb];
        p1 = *(const uint2*)&Kl0[(m0 + g + 8) * KROW + kb];
        ql[kf][0] = p0.x; ql[kf][1] = p1.x; ql[kf][2] = p0.y; ql[kf][3] = p1.y;
    }
    __syncthreads();

    float o[16][4];
    #pragma unroll
    for (int nd = 0; nd < 16; nd++)
        #pragma unroll
        for (int q = 0; q < 4; q++) o[nd][q] = 0.f;
    float mrow0 = -INFINITY, mrow1 = -INFINITY;
    float lsum0 = 0.f, lsum1 = 0.f;

    const unsigned* Vhw = (const unsigned*)g_vT_hi;
    const unsigned* Vlw = (const unsigned*)g_vT_lo;

    auto issue = [&](int kt, int bi) {
        unsigned dKh = sbase + (bi * KBUF) * 4;
        unsigned dKl = sbase + (2*KBUF + bi * KBUF) * 4;
        unsigned dVh = sbase + (4*KBUF + bi * VBUF) * 4;
        unsigned dVl = sbase + (4*KBUF + 2*VBUF + bi * VBUF) * 4;
        #pragma unroll
        for (int i = 0; i < 4; i++) {
            int c = t + 256 * i;
            int r = c >> 4, cw = (c & 15) * 4;
            size_t goff = (size_t)(b * Sq + kt * 64 + r) * (Dd/2) + cw;
            cp16(dKh + (r * KROW + cw) * 4, &g_k_hi[goff]);
            cp16(dKl + (r * KROW + cw) * 4, &g_k_lo[goff]);
        }
        #pragma unroll
        for (int i = 0; i < 4; i++) {
            int c = t + 256 * i;
            int r = c >> 3, cw = (c & 7) * 4;
            size_t goff = (size_t)r * (MM/2) + (size_t)(b * Sq + kt * 64) / 2 + cw;
            cp16(dVh + (r * VROW + cw) * 4, &Vhw[goff]);
            cp16(dVl + (r * VROW + cw) * 4, &Vlw[goff]);
        }
    };

    issue(0, 0);
    cp_commit();

    for (int kt = 0; kt < NT_TILES; kt++) {
        const int bi = kt & 1;
        if (kt + 1 < NT_TILES) { issue(kt + 1, bi ^ 1); cp_commit(); cp_wait<1>(); }
        else                   { cp_wait<0>(); }
        __syncthreads();

        unsigned* Kh = Kh0 + bi * KBUF;
        unsigned* Kl = Kl0 + bi * KBUF;
        unsigned* Vh = Vh0 + bi * VBUF;
        unsigned* Vl = Vl0 + bi * VBUF;

        float s[8][4];
        #pragma unroll
        for (int nt = 0; nt < 8; nt++)
            #pragma unroll
            for (int q = 0; q < 4; q++) s[nt][q] = 0.f;

        #pragma unroll
        for (int kf = 0; kf < 8; kf++) {
            const int kb = kf * 8 + 2 * tig;
            #pragma unroll
            for (int nt = 0; nt < 8; nt++) {
                int nc = nt * 8 + g;
                uint2 bhp = *(const uint2*)&Kh[nc * KROW + kb];
                uint2 blp = *(const uint2*)&Kl[nc * KROW + kb];
                mma_bf16(s[nt], qh[kf][0], qh[kf][1], qh[kf][2], qh[kf][3], blp.x, blp.y);
                mma_bf16(s[nt], ql[kf][0], ql[kf][1], ql[kf][2], ql[kf][3], bhp.x, bhp.y);
                mma_bf16(s[nt], qh[kf][0], qh[kf][1], qh[kf][2], qh[kf][3], bhp.x, bhp.y);
            }
        }

        float m0new = -INFINITY, m1new = -INFINITY;
        #pragma unroll
        for (int nt = 0; nt < 8; nt++) {
            int c0 = kt * 64 + nt * 8 + tig * 2;
            float mt0 = (1.0f - maskrow[c0])     * NEG;
            float mt1 = (1.0f - maskrow[c0 + 1]) * NEG;
            s[nt][0] = s[nt][0] * scale + mt0;
            s[nt][1] = s[nt][1] * scale + mt1;
            s[nt][2] = s[nt][2] * scale + mt0;
            s[nt][3] = s[nt][3] * scale + mt1;
            m0new = fmaxf(m0new, fmaxf(s[nt][0], s[nt][1]));
            m1new = fmaxf(m1new, fmaxf(s[nt][2], s[nt][3]));
        }
        m0new = fmaxf(m0new, __shfl_xor_sync(0xffffffffu, m0new, 1));
        m0new = fmaxf(m0new, __shfl_xor_sync(0xffffffffu, m0new, 2));
        m1new = fmaxf(m1new, __shfl_xor_sync(0xffffffffu, m1new, 1));
        m1new = fmaxf(m1new, __shfl_xor_sync(0xffffffffu, m1new, 2));

        float newm0 = fmaxf(mrow0, m0new);
        float newm1 = fmaxf(mrow1, m1new);
        float corr0 = __expf(mrow0 - newm0);
        float corr1 = __expf(mrow1 - newm1);
        mrow0 = newm0; mrow1 = newm1;

        float ps0 = 0.f, ps1 = 0.f;
        #pragma unroll
        for (int nt = 0; nt < 8; nt++) {
            s[nt][0] = __expf(s[nt][0] - newm0);
            s[nt][1] = __expf(s[nt][1] - newm0);
            s[nt][2] = __expf(s[nt][2] - newm1);
            s[nt][3] = __expf(s[nt][3] - newm1);
            ps0 += s[nt][0] + s[nt][1];
            ps1 += s[nt][2] + s[nt][3];
        }
        ps0 += __shfl_xor_sync(0xffffffffu, ps0, 1);
        ps0 += __shfl_xor_sync(0xffffffffu, ps0, 2);
        ps1 += __shfl_xor_sync(0xffffffffu, ps1, 1);
        ps1 += __shfl_xor_sync(0xffffffffu, ps1, 2);
        lsum0 = lsum0 * corr0 + ps0;
        lsum1 = lsum1 * corr1 + ps1;

        #pragma unroll
        for (int nd = 0; nd < 16; nd++) {
            o[nd][0] *= corr0; o[nd][1] *= corr0;
            o[nd][2] *= corr1; o[nd][3] *= corr1;
        }

        #pragma unroll
        for (int kf = 0; kf < 4; kf++) {
            unsigned a0h, a0l, a1h, a1l, a2h, a2l, a3h, a3l;
            split2(s[2*kf  ][0], s[2*kf  ][1], a0h, a0l);
            split2(s[2*kf  ][2], s[2*kf  ][3], a1h, a1l);
            split2(s[2*kf+1][0], s[2*kf+1][1], a2h, a2l);
            split2(s[2*kf+1][2], s[2*kf+1][3], a3h, a3l);
            const int kb = kf * 8 + 2 * tig;
            #pragma unroll
            for (int nd = 0; nd < 16; nd++) {
                int nc = nd * 8 + g;
                uint2 bhp = *(const uint2*)&Vh[nc * VROW + kb];
                uint2 blp = *(const uint2*)&Vl[nc * VROW + kb];
                mma_bf16(o[nd], a0h, a1h, a2h, a3h, blp.x, blp.y);
                mma_bf16(o[nd], a0l, a1l, a2l, a3l, bhp.x, bhp.y);
                mma_bf16(o[nd], a0h, a1h, a2h, a3h, bhp.x, bhp.y);
            }
        }
        __syncthreads();
    }

    // epilogue: normalize, split, permuted packed write
    float inv0 = 1.0f / lsum0;
    float inv1 = 1.0f / lsum1;
    size_t row0 = (size_t)(b * Sq + qt * 128 + m0 + g);
    #pragma unroll
    for (int nd = 0; nd < 16; nd++) {
        int cw = permw(h * (Dd/2) + nd * 4 + tig);
        unsigned hh, llw;
        split2(o[nd][0] * inv0, o[nd][1] * inv0, hh, llw);
        g_a_hi[row0 * (HID/2) + cw] = hh;
        g_a_lo[row0 * (HID/2) + cw] = llw;
        split2(o[nd][2] * inv1, o[nd][3] * inv1, hh, llw);
        g_a_hi[(row0 + 8) * (HID/2) + cw] = hh;
        g_a_lo[(row0 + 8) * (HID/2) + cw] = llw;
    }
}

// ---------------------------------------------------------------------------
extern "C" void kernel_launch(void* const* d_in, const int* in_sizes, int n_in,
                              void* d_out, int out_size)
{
    const float* hs   = (const float*)d_in[0];
    const float* mask = (const float*)d_in[1];
    const float* Wq   = (const float*)d_in[2];
    const float* Wk   = (const float*)d_in[3];
    const float* Wv   = (const float*)d_in[4];
    const float* Wo   = (const float*)d_in[5];
    float* out = (float*)d_out;

    void *hsh, *hsl, *wqh, *wql, *woh, *wol;
    cudaGetSymbolAddress(&hsh, g_hs_hi);  cudaGetSymbolAddress(&hsl, g_hs_lo);
    cudaGetSymbolAddress(&wqh, g_wq_hi);  cudaGetSymbolAddress(&wql, g_wq_lo);
    cudaGetSymbolAddress(&woh, g_wo_hi);  cudaGetSymbolAddress(&wol, g_wo_lo);

    cudaFuncSetAttribute(attn_kernel, cudaFuncAttributeMaxDynamicSharedMemorySize,
                         ATTN_SMEM_WORDS * 4);
    cudaFuncSetAttribute(gemm_qkv, cudaFuncAttributeMaxDynamicSharedMemorySize, GEMM_SMEM_BYTES);
    cudaFuncSetAttribute(gemm_o2,  cudaFuncAttributeMaxDynamicSharedMemorySize, GEMM_SMEM_BYTES);

    dim3 blk(256);
    // presplit inputs (permuted hi/lo word layout)
    presplit<<<MM*HID/16/256,  blk>>>(hs, (unsigned*)hsh, (unsigned*)hsl, MM*HID/16);
    presplit<<<HID*HID/16/256, blk>>>(Wq, (unsigned*)wqh, (unsigned*)wql, HID*HID/16);
    presplit_kv<<<dim3(Dd*HID/16/256, 2), blk>>>(Wk, Wv, Dd*HID/16);
    presplit<<<HID*HID/16/256, blk>>>(Wo, (unsigned*)woh, (unsigned*)wol, HID*HID/16);

    // merged Q/K/V projections (+ direct KV cache output writes)
    gemm_qkv<<<dim3(18, MM / BM), blk, GEMM_SMEM_BYTES>>>(out, MM, HID);
    // attention
    attn_kernel<<<dim3(Sq / 128, Bz * Hh), blk, ATTN_SMEM_WORDS * 4>>>(mask);
    // output projection
    gemm_o2<<<dim3(HID / BN, MM / BM), blk, GEMM_SMEM_BYTES>>>(out, MM, HID, HID);
}

// round 13
// speedup vs baseline: 1.5021x; 1.3826x over previous
#include <cuda_runtime.h>
#include <cuda_fp16.h>
#include <math.h>

#define Bz   2
#define Sq   2048
#define Hh   16
#define Dd   128
#define HID  2048
#define MM   (Bz*Sq)        // 4096

// ---------------- scratch (static device globals; no allocs) ----------------
// permuted packed fp16x2 words: groups of 8 words stored [w0,w4,w1,w5,w2,w6,w3,w7]
// A-side operands keep hi+lo; B-side operands are hi-only.
__device__ __align__(16) unsigned g_hs_hi[MM*(HID/2)], g_hs_lo[MM*(HID/2)];
__device__ __align__(16) unsigned g_wq_h[HID*(HID/2)];
__device__ __align__(16) unsigned g_wk_h[Dd*(HID/2)];
__device__ __align__(16) unsigned g_wv_h[Dd*(HID/2)];
__device__ __align__(16) unsigned g_wo_h[HID*(HID/2)];
__device__ __align__(16) unsigned g_q_hi[MM*(HID/2)],  g_q_lo[MM*(HID/2)];
__device__ __align__(16) unsigned g_k_h[MM*(Dd/2)];
__device__ __align__(16) __half   g_vT_h[Dd*MM];          // V^T hi, permuted s
__device__ __align__(16) unsigned g_a_hi[MM*(HID/2)],  g_a_lo[MM*(HID/2)];

// ---------------------------------------------------------------------------
// helpers
// ---------------------------------------------------------------------------
__device__ __forceinline__ void split2h(float x0, float x1, unsigned& hi, unsigned& lo)
{
    __half h0 = __float2half_rn(x0);
    __half h1 = __float2half_rn(x1);
    __half l0 = __float2half_rn(x0 - __half2float(h0));
    __half l1 = __float2half_rn(x1 - __half2float(h1));
    hi = ((unsigned)__half_as_ushort(h1) << 16) | (unsigned)__half_as_ushort(h0);
    lo = ((unsigned)__half_as_ushort(l1) << 16) | (unsigned)__half_as_ushort(l0);
}

__device__ __forceinline__ unsigned pack2h(float x0, float x1)
{
    __half h0 = __float2half_rn(x0);
    __half h1 = __float2half_rn(x1);
    return ((unsigned)__half_as_ushort(h1) << 16) | (unsigned)__half_as_ushort(h0);
}

__device__ __forceinline__ void mma_f16(float c[4],
    unsigned a0, unsigned a1, unsigned a2, unsigned a3,
    unsigned b0, unsigned b1)
{
    asm volatile(
        "mma.sync.aligned.m16n8k16.row.col.f32.f16.f16.f32 "
        "{%0,%1,%2,%3}, {%4,%5,%6,%7}, {%8,%9}, {%0,%1,%2,%3};"
        : "+f"(c[0]), "+f"(c[1]), "+f"(c[2]), "+f"(c[3])
        : "r"(a0), "r"(a1), "r"(a2), "r"(a3), "r"(b0), "r"(b1));
}

__device__ __forceinline__ void cp16(unsigned dst, const void* src)
{
    asm volatile("cp.async.cg.shared.global [%0], [%1], 16;" :: "r"(dst), "l"(src));
}
__device__ __forceinline__ void cp_commit()
{
    asm volatile("cp.async.commit_group;");
}
template<int N>
__device__ __forceinline__ void cp_wait()
{
    asm volatile("cp.async.wait_group %0;" :: "n"(N));
}

__device__ __forceinline__ int permw(int w)
{
    int ww = w & 7;
    int slot = (ww < 4) ? (2 * ww) : (2 * ww - 7);
    return (w & ~7) | slot;
}

__device__ __forceinline__ unsigned smem_u32(const void* p)
{
    return (unsigned)__cvta_generic_to_shared(p);
}

// ---------------------------------------------------------------------------
// presplit kernels (permuted word order)
// ---------------------------------------------------------------------------
__global__ __launch_bounds__(256)
void presplit_a(const float* __restrict__ X, unsigned* __restrict__ Hi,
                unsigned* __restrict__ Lo, int ngroups)
{
    int gi = blockIdx.x * 256 + threadIdx.x;
    if (gi >= ngroups) return;
    const float4* src = (const float4*)X + (size_t)gi * 4;
    unsigned wh[8], wl[8];
    #pragma unroll
    for (int i = 0; i < 4; i++) {
        float4 v = src[i];
        split2h(v.x, v.y, wh[2*i],   wl[2*i]);
        split2h(v.z, v.w, wh[2*i+1], wl[2*i+1]);
    }
    uint4 h0 = {wh[0], wh[4], wh[1], wh[5]};
    uint4 h1 = {wh[2], wh[6], wh[3], wh[7]};
    uint4 l0 = {wl[0], wl[4], wl[1], wl[5]};
    uint4 l1 = {wl[2], wl[6], wl[3], wl[7]};
    ((uint4*)Hi)[(size_t)gi*2]   = h0;  ((uint4*)Hi)[(size_t)gi*2+1] = h1;
    ((uint4*)Lo)[(size_t)gi*2]   = l0;  ((uint4*)Lo)[(size_t)gi*2+1] = l1;
}

__device__ __forceinline__ void presplit_b_one(const float* __restrict__ X,
    unsigned* __restrict__ Hi, int gi)
{
    const float4* src = (const float4*)X + (size_t)gi * 4;
    unsigned wh[8];
    #pragma unroll
    for (int i = 0; i < 4; i++) {
        float4 v = src[i];
        wh[2*i]   = pack2h(v.x, v.y);
        wh[2*i+1] = pack2h(v.z, v.w);
    }
    uint4 h0 = {wh[0], wh[4], wh[1], wh[5]};
    uint4 h1 = {wh[2], wh[6], wh[3], wh[7]};
    ((uint4*)Hi)[(size_t)gi*2]   = h0;
    ((uint4*)Hi)[(size_t)gi*2+1] = h1;
}

// pair of B matrices selected by blockIdx.y
__global__ __launch_bounds__(256)
void presplit_b_pair(const float* __restrict__ X0, unsigned* __restrict__ H0,
                     const float* __restrict__ X1, unsigned* __restrict__ H1,
                     int ngroups)
{
    int gi = blockIdx.x * 256 + threadIdx.x;
    if (gi >= ngroups) return;
    if (blockIdx.y == 0) presplit_b_one(X0, H0, gi);
    else                 presplit_b_one(X1, H1, gi);
}

// ---------------------------------------------------------------------------
// warp-mma 2xFP16 GEMM core: C = A @ W^T with A split hi/lo, B hi-only.
// 128x128 block, BK=32 (16 words), 256 threads (8 warps 4x2),
// cp.async 2-stage double buffer, LDS.64 fragment loads.
// ---------------------------------------------------------------------------
#define BM 128
#define BN 128
#define GWS 24
#define GST (BM*GWS)
#define GEMM_SMEM_BYTES (6*GST*4)    // Ah,Al,Bh x 2 stages

__device__ __forceinline__ void gemm_core3(
    const unsigned* __restrict__ Ahi, const unsigned* __restrict__ Alo,
    const unsigned* __restrict__ Bh,
    int KW, int bm, int bn, unsigned* dsm, float acc[2][8][4])
{
    unsigned* sAh = dsm;
    unsigned* sAl = dsm + 2*GST;
    unsigned* sBh = dsm + 4*GST;
    const unsigned sbase = smem_u32(dsm);

    const int t    = threadIdx.x;
    const int lane = t & 31, w = t >> 5;
    const int g    = lane >> 2, tig = lane & 3;
    const int wm   = w >> 1, wn = w & 1;

    #pragma unroll
    for (int i = 0; i < 2; i++)
        #pragma unroll
        for (int j = 0; j < 8; j++)
            #pragma unroll
            for (int q = 0; q < 4; q++) acc[i][j][q] = 0.f;

    const int cr = t >> 2, cc4 = (t & 3) * 4;
    auto issue = [&](int it, int bi) {
        const int kw0 = it * 16;
        unsigned dAh = sbase + (0*GST*2 + bi*GST) * 4;
        unsigned dAl = sbase + (1*GST*2 + bi*GST) * 4;
        unsigned dBh = sbase + (2*GST*2 + bi*GST) * 4;
        #pragma unroll
        for (int i = 0; i < 2; i++) {
            int r = cr + 64 * i;
            size_t ao = (size_t)(bm + r) * KW + kw0 + cc4;
            size_t bo = (size_t)(bn + r) * KW + kw0 + cc4;
            unsigned so = (r * GWS + cc4) * 4;
            cp16(dAh + so, &Ahi[ao]);
            cp16(dAl + so, &Alo[ao]);
            cp16(dBh + so, &Bh[bo]);
        }
    };

    const int niter = KW / 16;
    issue(0, 0);
    cp_commit();

    for (int it = 0; it < niter; it++) {
        if (it + 1 < niter) { issue(it + 1, (it + 1) & 1); cp_commit(); cp_wait<1>(); }
        else                { cp_wait<0>(); }
        __syncthreads();

        const int bi = it & 1;
        const unsigned* pAh = sAh + bi * GST;
        const unsigned* pAl = sAl + bi * GST;
        const unsigned* pBh = sBh + bi * GST;

        #pragma unroll
        for (int ks = 0; ks < 2; ks++) {
            const int kb = ks * 8 + 2 * tig;
            uint2 ah0[2], ah1[2], al0[2], al1[2];
            #pragma unroll
            for (int mt = 0; mt < 2; mt++) {
                int m0r = wm * 32 + mt * 16;
                ah0[mt] = *(const uint2*)&pAh[(m0r + g    ) * GWS + kb];
                ah1[mt] = *(const uint2*)&pAh[(m0r + g + 8) * GWS + kb];
                al0[mt] = *(const uint2*)&pAl[(m0r + g    ) * GWS + kb];
                al1[mt] = *(const uint2*)&pAl[(m0r + g + 8) * GWS + kb];
            }
            #pragma unroll
            for (int nt = 0; nt < 8; nt++) {
                int nc = wn * 64 + nt * 8 + g;
                uint2 bhp = *(const uint2*)&pBh[nc * GWS + kb];
                #pragma unroll
                for (int mt = 0; mt < 2; mt++) {
                    mma_f16(acc[mt][nt], ah0[mt].x, ah1[mt].x, ah0[mt].y, ah1[mt].y, bhp.x, bhp.y);
                    mma_f16(acc[mt][nt], al0[mt].x, al1[mt].x, al0[mt].y, al1[mt].y, bhp.x, bhp.y);
                }
            }
        }
        __syncthreads();
    }
}

// ---------------------------------------------------------------------------
// merged Q/K/V projection: grid (18, 32). x<16: Q tile; x==16: K; x==17: V.
// K/V epilogues also write the 16-head-replicated cache outputs directly.
// ---------------------------------------------------------------------------
__global__ __launch_bounds__(256, 2)
void gemm_qkv(float* __restrict__ out, int M, int K)
{
    extern __shared__ unsigned dsm[];
    float acc[2][8][4];
    const int bm = blockIdx.y * BM;
    const int bx = blockIdx.x;

    const unsigned *Bhp;
    int bn;
    if (bx < 16)      { Bhp = g_wq_h; bn = bx * BN; }
    else if (bx == 16){ Bhp = g_wk_h; bn = 0; }
    else              { Bhp = g_wv_h; bn = 0; }

    gemm_core3(g_hs_hi, g_hs_lo, Bhp, K >> 1, bm, bn, dsm, acc);

    const int t = threadIdx.x, lane = t & 31, w = t >> 5;
    const int g = lane >> 2, tig = lane & 3;
    const int wm = w >> 1, wn = w & 1;

    if (bx < 16) {
        // ---- Q epilogue: split + permuted packed ----
        const int NW = HID >> 1;
        #pragma unroll
        for (int mt = 0; mt < 2; mt++) {
            int r0 = bm + wm * 32 + mt * 16 + g;
            #pragma unroll
            for (int nt = 0; nt < 8; nt++) {
                int wp = permw((bn >> 1) + wn * 32 + nt * 4 + tig);
                unsigned h0, l0;
                split2h(acc[mt][nt][0], acc[mt][nt][1], h0, l0);
                g_q_hi[(size_t)r0 * NW + wp] = h0;
                g_q_lo[(size_t)r0 * NW + wp] = l0;
                split2h(acc[mt][nt][2], acc[mt][nt][3], h0, l0);
                g_q_hi[(size_t)(r0 + 8) * NW + wp] = h0;
                g_q_lo[(size_t)(r0 + 8) * NW + wp] = l0;
            }
        }
        return;
    }

    // ---- K / V epilogues ----
    const int NW = Dd >> 1;
    const size_t keybase = (size_t)MM * HID;                       // 8388608
    const size_t valbase = keybase + (size_t)Bz * Hh * Sq * Dd;    // 16777216
    const size_t cachebase = (bx == 16) ? keybase : valbase;

    #pragma unroll
    for (int mt = 0; mt < 2; mt++) {
        int r0 = bm + wm * 32 + mt * 16 + g;
        #pragma unroll
        for (int nt = 0; nt < 8; nt++) {
            int c0 = wn * 64 + nt * 8 + tig * 2;
            float a0 = acc[mt][nt][0], a1 = acc[mt][nt][1];
            float a2 = acc[mt][nt][2], a3 = acc[mt][nt][3];

            // 16-head replicated cache output (rows r0 and r0+8)
            #pragma unroll
            for (int rr = 0; rr < 2; rr++) {
                int r = r0 + rr * 8;
                int b = r >> 11;
                int s = r & (Sq - 1);
                float2 v2 = rr ? make_float2(a2, a3) : make_float2(a0, a1);
                size_t base = cachebase + ((size_t)b * Hh * Sq + s) * Dd + c0;
                #pragma unroll
                for (int h = 0; h < Hh; h++)
                    *(float2*)&out[base + (size_t)h * Sq * Dd] = v2;
            }

            if (bx == 16) {
                // K: hi-only permuted packed
                int wp = permw(c0 >> 1);
                g_k_h[(size_t)r0 * NW + wp]       = pack2h(a0, a1);
                g_k_h[(size_t)(r0 + 8) * NW + wp] = pack2h(a2, a3);
            } else {
                // V: transposed hi-only with permuted s-position
                #pragma unroll
                for (int q = 0; q < 4; q++) {
                    float val = acc[mt][nt][q];
                    int cc = c0 + (q & 1);
                    int rr = r0 + (q >> 1) * 8;
                    int sp = permw(rr >> 1) * 2 + (rr & 1);
                    g_vT_h[(size_t)cc * MM + sp] = __float2half_rn(val);
                }
            }
        }
    }
}

// ---- O projection: fp32 output ---------------------------------------------
__global__ __launch_bounds__(256, 2)
void gemm_o2(float* __restrict__ C, int M, int N, int K)
{
    extern __shared__ unsigned dsm[];
    float acc[2][8][4];
    const int bm = blockIdx.y * BM, bn = blockIdx.x * BN;
    gemm_core3(g_a_hi, g_a_lo, g_wo_h, K >> 1, bm, bn, dsm, acc);

    const int t = threadIdx.x, lane = t & 31, w = t >> 5;
    const int g = lane >> 2, tig = lane & 3;
    const int wm = w >> 1, wn = w & 1;
    #pragma unroll
    for (int mt = 0; mt < 2; mt++) {
        int r0 = bm + wm * 32 + mt * 16 + g;
        #pragma unroll
        for (int nt = 0; nt < 8; nt++) {
            int c0 = bn + wn * 64 + nt * 8 + tig * 2;
            *(float2*)&C[(size_t)r0 * N + c0]       = make_float2(acc[mt][nt][0], acc[mt][nt][1]);
            *(float2*)&C[(size_t)(r0 + 8) * N + c0] = make_float2(acc[mt][nt][2], acc[mt][nt][3]);
        }
    }
}

// ---------------------------------------------------------------------------
// FlashAttention-2, 2xFP16: K and V are hi-only in smem -> half the smem
// bandwidth, 2 mma per fragment. Register softmax, cp.async double buffer.
// K rows: 32 data words + 8 pad? No: 64 data words... K tile = 64 keys x 128d
// -> 64 words/row hi. KROW=72 (64+8). V: 32 words/row hi, VROW=40.
// ---------------------------------------------------------------------------
#define KROW 72
#define VROW 40
#define KBUF (64*KROW)     // 4608 words per stage (hi only)
#define VBUF (128*VROW)    // 5120 words per stage (hi only)
#define ATTN_SMEM_WORDS (2*KBUF + 2*VBUF + Sq)   // 21504 words = 86KB
#define NT_TILES (Sq/64)

__global__ __launch_bounds__(256, 1)
void attn_kernel(const float* __restrict__ mask)
{
    extern __shared__ unsigned smw[];
    unsigned* Kh0 = smw;                    // 2 stages
    unsigned* Vh0 = smw + 2*KBUF;           // 2 stages
    float*  maskrow = (float*)(smw + 2*KBUF + 2*VBUF);

    const unsigned sbase = smem_u32(smw);

    const int t    = threadIdx.x;
    const int lane = t & 31, w = t >> 5;
    const int g    = lane >> 2, tig = lane & 3;
    const int qt   = blockIdx.x;
    const int bh   = blockIdx.y;
    const int b    = bh / Hh;
    const int h    = bh % Hh;
    const int m0   = w * 16;

    const float scale = 0.08838834764831845f;
    const float NEG   = -3.402823466e38f;

    #pragma unroll
    for (int i = 0; i < 2; i++) {
        int c = t + 256 * i;
        *(float4*)&maskrow[c * 4] = *(const float4*)&mask[b * Sq + c * 4];
    }

    // ---- stage Q (128 rows x 64 words): hi into K area, lo into V area ----
    #pragma unroll
    for (int i = 0; i < 8; i++) {
        int c = t + 256 * i;
        int r = c >> 4, cw = (c & 15) * 4;
        size_t goff = (size_t)(b * Sq + qt * 128 + r) * (HID/2) + h * (Dd/2) + cw;
        *(uint4*)&Kh0[r * KROW + cw] = *(const uint4*)&g_q_hi[goff];
        *(uint4*)&Vh0[r * KROW + cw] = *(const uint4*)&g_q_lo[goff];
    }
    __syncthreads();

    unsigned qh[8][4], ql[8][4];
    #pragma unroll
    for (int kf = 0; kf < 8; kf++) {
        int kb = kf * 8 + 2 * tig;
        uint2 p0 = *(const uint2*)&Kh0[(m0 + g    ) * KROW + kb];
        uint2 p1 = *(const uint2*)&Kh0[(m0 + g + 8) * KROW + kb];
        qh[kf][0] = p0.x; qh[kf][1] = p1.x; qh[kf][2] = p0.y; qh[kf][3] = p1.y;
        p0 = *(const uint2*)&Vh0[(m0 + g    ) * KROW + kb];
        p1 = *(const uint2*)&Vh0[(m0 + g + 8) * KROW + kb];
        ql[kf][0] = p0.x; ql[kf][1] = p1.x; ql[kf][2] = p0.y; ql[kf][3] = p1.y;
    }
    __syncthreads();

    float o[16][4];
    #pragma unroll
    for (int nd = 0; nd < 16; nd++)
        #pragma unroll
        for (int q = 0; q < 4; q++) o[nd][q] = 0.f;
    float mrow0 = -INFINITY, mrow1 = -INFINITY;
    float lsum0 = 0.f, lsum1 = 0.f;

    const unsigned* Vhw = (const unsigned*)g_vT_h;

    auto issue = [&](int kt, int bi) {
        unsigned dKh = sbase + (bi * KBUF) * 4;
        unsigned dVh = sbase + (2*KBUF + bi * VBUF) * 4;
        #pragma unroll
        for (int i = 0; i < 4; i++) {
            int c = t + 256 * i;               // 1024 K chunks
            int r = c >> 4, cw = (c & 15) * 4;
            size_t goff = (size_t)(b * Sq + kt * 64 + r) * (Dd/2) + cw;
            cp16(dKh + (r * KROW + cw) * 4, &g_k_h[goff]);
        }
        #pragma unroll
        for (int i = 0; i < 4; i++) {
            int c = t + 256 * i;               // 1024 V chunks
            int r = c >> 3, cw = (c & 7) * 4;
            size_t goff = (size_t)r * (MM/2) + (size_t)(b * Sq + kt * 64) / 2 + cw;
            cp16(dVh + (r * VROW + cw) * 4, &Vhw[goff]);
        }
    };

    issue(0, 0);
    cp_commit();

    for (int kt = 0; kt < NT_TILES; kt++) {
        const int bi = kt & 1;
        if (kt + 1 < NT_TILES) { issue(kt + 1, bi ^ 1); cp_commit(); cp_wait<1>(); }
        else                   { cp_wait<0>(); }
        __syncthreads();

        unsigned* Kh = Kh0 + bi * KBUF;
        unsigned* Vh = Vh0 + bi * VBUF;

        // ----- QK^T : hi-only B fragments, 2 mma each
        float s[8][4];
        #pragma unroll
        for (int nt = 0; nt < 8; nt++)
            #pragma unroll
            for (int q = 0; q < 4; q++) s[nt][q] = 0.f;

        #pragma unroll
        for (int kf = 0; kf < 8; kf++) {
            const int kb = kf * 8 + 2 * tig;
            #pragma unroll
            for (int nt = 0; nt < 8; nt++) {
                int nc = nt * 8 + g;
                uint2 bhp = *(const uint2*)&Kh[nc * KROW + kb];
                mma_f16(s[nt], qh[kf][0], qh[kf][1], qh[kf][2], qh[kf][3], bhp.x, bhp.y);
                mma_f16(s[nt], ql[kf][0], ql[kf][1], ql[kf][2], ql[kf][3], bhp.x, bhp.y);
            }
        }

        // ----- scale + mask + register softmax
        float m0new = -INFINITY, m1new = -INFINITY;
        #pragma unroll
        for (int nt = 0; nt < 8; nt++) {
            int c0 = kt * 64 + nt * 8 + tig * 2;
            float mt0 = (1.0f - maskrow[c0])     * NEG;
            float mt1 = (1.0f - maskrow[c0 + 1]) * NEG;
            s[nt][0] = s[nt][0] * scale + mt0;
            s[nt][1] = s[nt][1] * scale + mt1;
            s[nt][2] = s[nt][2] * scale + mt0;
            s[nt][3] = s[nt][3] * scale + mt1;
            m0new = fmaxf(m0new, fmaxf(s[nt][0], s[nt][1]));
            m1new = fmaxf(m1new, fmaxf(s[nt][2], s[nt][3]));
        }
        m0new = fmaxf(m0new, __shfl_xor_sync(0xffffffffu, m0new, 1));
        m0new = fmaxf(m0new, __shfl_xor_sync(0xffffffffu, m0new, 2));
        m1new = fmaxf(m1new, __shfl_xor_sync(0xffffffffu, m1new, 1));
        m1new = fmaxf(m1new, __shfl_xor_sync(0xffffffffu, m1new, 2));

        float newm0 = fmaxf(mrow0, m0new);
        float newm1 = fmaxf(mrow1, m1new);
        float corr0 = __expf(mrow0 - newm0);
        float corr1 = __expf(mrow1 - newm1);
        mrow0 = newm0; mrow1 = newm1;

        float ps0 = 0.f, ps1 = 0.f;
        #pragma unroll
        for (int nt = 0; nt < 8; nt++) {
            s[nt][0] = __expf(s[nt][0] - newm0);
            s[nt][1] = __expf(s[nt][1] - newm0);
            s[nt][2] = __expf(s[nt][2] - newm1);
            s[nt][3] = __expf(s[nt][3] - newm1);
            ps0 += s[nt][0] + s[nt][1];
            ps1 += s[nt][2] + s[nt][3];
        }
        ps0 += __shfl_xor_sync(0xffffffffu, ps0, 1);
        ps0 += __shfl_xor_sync(0xffffffffu, ps0, 2);
        ps1 += __shfl_xor_sync(0xffffffffu, ps1, 1);
        ps1 += __shfl_xor_sync(0xffffffffu, ps1, 2);
        lsum0 = lsum0 * corr0 + ps0;
        lsum1 = lsum1 * corr1 + ps1;

        #pragma unroll
        for (int nd = 0; nd < 16; nd++) {
            o[nd][0] *= corr0; o[nd][1] *= corr0;
            o[nd][2] *= corr1; o[nd][3] *= corr1;
        }

        // ----- PV : P split in regs (A-side), V hi-only, 2 mma each
        #pragma unroll
        for (int kf = 0; kf < 4; kf++) {
            unsigned a0h, a0l, a1h, a1l, a2h, a2l, a3h, a3l;
            split2h(s[2*kf  ][0], s[2*kf  ][1], a0h, a0l);
            split2h(s[2*kf  ][2], s[2*kf  ][3], a1h, a1l);
            split2h(s[2*kf+1][0], s[2*kf+1][1], a2h, a2l);
            split2h(s[2*kf+1][2], s[2*kf+1][3], a3h, a3l);
            const int kb = kf * 8 + 2 * tig;
            #pragma unroll
            for (int nd = 0; nd < 16; nd++) {
                int nc = nd * 8 + g;
                uint2 vhp = *(const uint2*)&Vh[nc * VROW + kb];
                mma_f16(o[nd], a0h, a1h, a2h, a3h, vhp.x, vhp.y);
                mma_f16(o[nd], a0l, a1l, a2l, a3l, vhp.x, vhp.y);
            }
        }
        __syncthreads();
    }

    // epilogue: normalize, split, permuted packed write
    float inv0 = 1.0f / lsum0;
    float inv1 = 1.0f / lsum1;
    size_t row0 = (size_t)(b * Sq + qt * 128 + m0 + g);
    #pragma unroll
    for (int nd = 0; nd < 16; nd++) {
        int cw = permw(h * (Dd/2) + nd * 4 + tig);
        unsigned hh, llw;
        split2h(o[nd][0] * inv0, o[nd][1] * inv0, hh, llw);
        g_a_hi[row0 * (HID/2) + cw] = hh;
        g_a_lo[row0 * (HID/2) + cw] = llw;
        split2h(o[nd][2] * inv1, o[nd][3] * inv1, hh, llw);
        g_a_hi[(row0 + 8) * (HID/2) + cw] = hh;
        g_a_lo[(row0 + 8) * (HID/2) + cw] = llw;
    }
}

// ---------------------------------------------------------------------------
extern "C" void kernel_launch(void* const* d_in, const int* in_sizes, int n_in,
                              void* d_out, int out_size)
{
    const float* hs   = (const float*)d_in[0];
    const float* mask = (const float*)d_in[1];
    const float* Wq   = (const float*)d_in[2];
    const float* Wk   = (const float*)d_in[3];
    const float* Wv   = (const float*)d_in[4];
    const float* Wo   = (const float*)d_in[5];
    float* out = (float*)d_out;

    void *hsh, *hsl, *wqh, *wkh, *wvh, *woh;
    cudaGetSymbolAddress(&hsh, g_hs_hi);  cudaGetSymbolAddress(&hsl, g_hs_lo);
    cudaGetSymbolAddress(&wqh, g_wq_h);
    cudaGetSymbolAddress(&wkh, g_wk_h);
    cudaGetSymbolAddress(&wvh, g_wv_h);
    cudaGetSymbolAddress(&woh, g_wo_h);

    cudaFuncSetAttribute(attn_kernel, cudaFuncAttributeMaxDynamicSharedMemorySize,
                         ATTN_SMEM_WORDS * 4);
    cudaFuncSetAttribute(gemm_qkv, cudaFuncAttributeMaxDynamicSharedMemorySize, GEMM_SMEM_BYTES);
    cudaFuncSetAttribute(gemm_o2,  cudaFuncAttributeMaxDynamicSharedMemorySize, GEMM_SMEM_BYTES);

    dim3 blk(256);
    // presplits: hs -> hi/lo, weights -> hi only
    presplit_a<<<MM*HID/16/256, blk>>>(hs, (unsigned*)hsh, (unsigned*)hsl, MM*HID/16);
    presplit_b_pair<<<dim3(HID*HID/16/256, 2), blk>>>(Wq, (unsigned*)wqh,
                                                      Wo, (unsigned*)woh, HID*HID/16);
    presplit_b_pair<<<dim3(Dd*HID/16/256, 2), blk>>>(Wk, (unsigned*)wkh,
                                                     Wv, (unsigned*)wvh, Dd*HID/16);

    // merged Q/K/V projections (+ direct KV cache output writes)
    gemm_qkv<<<dim3(18, MM / BM), blk, GEMM_SMEM_BYTES>>>(out, MM, HID);
    // attention
    attn_kernel<<<dim3(Sq / 128, Bz * Hh), blk, ATTN_SMEM_WORDS * 4>>>(mask);
    // output projection
    gemm_o2<<<dim3(HID / BN, MM / BM), blk, GEMM_SMEM_BYTES>>>(out, MM, HID, HID);
}

// round 15
// speedup vs baseline: 1.5865x; 1.0562x over previous
#include <cuda_runtime.h>
#include <cuda_fp16.h>
#include <math.h>

#define Bz   2
#define Sq   2048
#define Hh   16
#define Dd   128
#define HID  2048
#define MM   (Bz*Sq)        // 4096

// ---------------- scratch (static device globals; no allocs) ----------------
__device__ __align__(16) unsigned g_hs_hi[MM*(HID/2)], g_hs_lo[MM*(HID/2)];
__device__ __align__(16) unsigned g_wq_h[HID*(HID/2)];
__device__ __align__(16) unsigned g_wk_h[Dd*(HID/2)];
__device__ __align__(16) unsigned g_wv_h[Dd*(HID/2)];
__device__ __align__(16) unsigned g_wo_h[HID*(HID/2)];
__device__ __align__(16) unsigned g_q_hi[MM*(HID/2)],  g_q_lo[MM*(HID/2)];
__device__ __align__(16) unsigned g_k_h[MM*(Dd/2)];
__device__ __align__(16) __half   g_vT_h[Dd*MM];          // V^T hi, permuted s
__device__ __align__(16) unsigned g_a_hi[MM*(HID/2)],  g_a_lo[MM*(HID/2)];

// ---------------------------------------------------------------------------
// helpers
// ---------------------------------------------------------------------------
__device__ __forceinline__ void split2h(float x0, float x1, unsigned& hi, unsigned& lo)
{
    __half h0 = __float2half_rn(x0);
    __half h1 = __float2half_rn(x1);
    __half l0 = __float2half_rn(x0 - __half2float(h0));
    __half l1 = __float2half_rn(x1 - __half2float(h1));
    hi = ((unsigned)__half_as_ushort(h1) << 16) | (unsigned)__half_as_ushort(h0);
    lo = ((unsigned)__half_as_ushort(l1) << 16) | (unsigned)__half_as_ushort(l0);
}

__device__ __forceinline__ unsigned pack2h(float x0, float x1)
{
    __half h0 = __float2half_rn(x0);
    __half h1 = __float2half_rn(x1);
    return ((unsigned)__half_as_ushort(h1) << 16) | (unsigned)__half_as_ushort(h0);
}

__device__ __forceinline__ void mma_f16(float c[4],
    unsigned a0, unsigned a1, unsigned a2, unsigned a3,
    unsigned b0, unsigned b1)
{
    asm volatile(
        "mma.sync.aligned.m16n8k16.row.col.f32.f16.f16.f32 "
        "{%0,%1,%2,%3}, {%4,%5,%6,%7}, {%8,%9}, {%0,%1,%2,%3};"
        : "+f"(c[0]), "+f"(c[1]), "+f"(c[2]), "+f"(c[3])
        : "r"(a0), "r"(a1), "r"(a2), "r"(a3), "r"(b0), "r"(b1));
}

__device__ __forceinline__ void cp16(unsigned dst, const void* src)
{
    asm volatile("cp.async.cg.shared.global [%0], [%1], 16;" :: "r"(dst), "l"(src));
}
__device__ __forceinline__ void cp_commit()
{
    asm volatile("cp.async.commit_group;");
}
template<int N>
__device__ __forceinline__ void cp_wait()
{
    asm volatile("cp.async.wait_group %0;" :: "n"(N));
}

__device__ __forceinline__ int permw(int w)
{
    int ww = w & 7;
    int slot = (ww < 4) ? (2 * ww) : (2 * ww - 7);
    return (w & ~7) | slot;
}

__device__ __forceinline__ unsigned smem_u32(const void* p)
{
    return (unsigned)__cvta_generic_to_shared(p);
}

// ---------------------------------------------------------------------------
// presplit kernels (permuted word order)
// ---------------------------------------------------------------------------
__global__ __launch_bounds__(256)
void presplit_a(const float* __restrict__ X, unsigned* __restrict__ Hi,
                unsigned* __restrict__ Lo, int ngroups)
{
    int gi = blockIdx.x * 256 + threadIdx.x;
    if (gi >= ngroups) return;
    const float4* src = (const float4*)X + (size_t)gi * 4;
    unsigned wh[8], wl[8];
    #pragma unroll
    for (int i = 0; i < 4; i++) {
        float4 v = src[i];
        split2h(v.x, v.y, wh[2*i],   wl[2*i]);
        split2h(v.z, v.w, wh[2*i+1], wl[2*i+1]);
    }
    uint4 h0 = {wh[0], wh[4], wh[1], wh[5]};
    uint4 h1 = {wh[2], wh[6], wh[3], wh[7]};
    uint4 l0 = {wl[0], wl[4], wl[1], wl[5]};
    uint4 l1 = {wl[2], wl[6], wl[3], wl[7]};
    ((uint4*)Hi)[(size_t)gi*2]   = h0;  ((uint4*)Hi)[(size_t)gi*2+1] = h1;
    ((uint4*)Lo)[(size_t)gi*2]   = l0;  ((uint4*)Lo)[(size_t)gi*2+1] = l1;
}

__device__ __forceinline__ void presplit_b_one(const float* __restrict__ X,
    unsigned* __restrict__ Hi, int gi)
{
    const float4* src = (const float4*)X + (size_t)gi * 4;
    unsigned wh[8];
    #pragma unroll
    for (int i = 0; i < 4; i++) {
        float4 v = src[i];
        wh[2*i]   = pack2h(v.x, v.y);
        wh[2*i+1] = pack2h(v.z, v.w);
    }
    uint4 h0 = {wh[0], wh[4], wh[1], wh[5]};
    uint4 h1 = {wh[2], wh[6], wh[3], wh[7]};
    ((uint4*)Hi)[(size_t)gi*2]   = h0;
    ((uint4*)Hi)[(size_t)gi*2+1] = h1;
}

// all 4 weight matrices in one launch (y: 0=Wq 1=Wo 2=Wk 3=Wv)
__global__ __launch_bounds__(256)
void presplit_w(const float* __restrict__ Wq, const float* __restrict__ Wo,
                const float* __restrict__ Wk, const float* __restrict__ Wv)
{
    int gi = blockIdx.x * 256 + threadIdx.x;
    int y = blockIdx.y;
    int ng = (y < 2) ? (HID*HID/16) : (Dd*HID/16);
    if (gi >= ng) return;
    if      (y == 0) presplit_b_one(Wq, g_wq_h, gi);
    else if (y == 1) presplit_b_one(Wo, g_wo_h, gi);
    else if (y == 2) presplit_b_one(Wk, g_wk_h, gi);
    else             presplit_b_one(Wv, g_wv_h, gi);
}

// ---------------------------------------------------------------------------
// warp-mma 2xFP16 GEMM core: C = A @ W^T with A split hi/lo, B hi-only.
// 128x128 block, BK=32 (16 words), 256 threads (8 warps 4x2),
// cp.async 2-stage double buffer, LDS.64 fragment loads.
// ---------------------------------------------------------------------------
#define BM 128
#define BN 128
#define GWS 24
#define GST (BM*GWS)
#define GEMM_SMEM_BYTES (6*GST*4)    // Ah,Al,Bh x 2 stages

__device__ __forceinline__ void gemm_core3(
    const unsigned* __restrict__ Ahi, const unsigned* __restrict__ Alo,
    const unsigned* __restrict__ Bh,
    int KW, int bm, int bn, unsigned* dsm, float acc[2][8][4])
{
    unsigned* sAh = dsm;
    unsigned* sAl = dsm + 2*GST;
    unsigned* sBh = dsm + 4*GST;
    const unsigned sbase = smem_u32(dsm);

    const int t    = threadIdx.x;
    const int lane = t & 31, w = t >> 5;
    const int g    = lane >> 2, tig = lane & 3;
    const int wm   = w >> 1, wn = w & 1;

    #pragma unroll
    for (int i = 0; i < 2; i++)
        #pragma unroll
        for (int j = 0; j < 8; j++)
            #pragma unroll
            for (int q = 0; q < 4; q++) acc[i][j][q] = 0.f;

    const int cr = t >> 2, cc4 = (t & 3) * 4;
    auto issue = [&](int it, int bi) {
        const int kw0 = it * 16;
        unsigned dAh = sbase + (0*GST*2 + bi*GST) * 4;
        unsigned dAl = sbase + (1*GST*2 + bi*GST) * 4;
        unsigned dBh = sbase + (2*GST*2 + bi*GST) * 4;
        #pragma unroll
        for (int i = 0; i < 2; i++) {
            int r = cr + 64 * i;
            size_t ao = (size_t)(bm + r) * KW + kw0 + cc4;
            size_t bo = (size_t)(bn + r) * KW + kw0 + cc4;
            unsigned so = (r * GWS + cc4) * 4;
            cp16(dAh + so, &Ahi[ao]);
            cp16(dAl + so, &Alo[ao]);
            cp16(dBh + so, &Bh[bo]);
        }
    };

    const int niter = KW / 16;
    issue(0, 0);
    cp_commit();

    for (int it = 0; it < niter; it++) {
        if (it + 1 < niter) { issue(it + 1, (it + 1) & 1); cp_commit(); cp_wait<1>(); }
        else                { cp_wait<0>(); }
        __syncthreads();

        const int bi = it & 1;
        const unsigned* pAh = sAh + bi * GST;
        const unsigned* pAl = sAl + bi * GST;
        const unsigned* pBh = sBh + bi * GST;

        #pragma unroll
        for (int ks = 0; ks < 2; ks++) {
            const int kb = ks * 8 + 2 * tig;
            uint2 ah0[2], ah1[2], al0[2], al1[2];
            #pragma unroll
            for (int mt = 0; mt < 2; mt++) {
                int m0r = wm * 32 + mt * 16;
                ah0[mt] = *(const uint2*)&pAh[(m0r + g    ) * GWS + kb];
                ah1[mt] = *(const uint2*)&pAh[(m0r + g + 8) * GWS + kb];
                al0[mt] = *(const uint2*)&pAl[(m0r + g    ) * GWS + kb];
                al1[mt] = *(const uint2*)&pAl[(m0r + g + 8) * GWS + kb];
            }
            #pragma unroll
            for (int nt = 0; nt < 8; nt++) {
                int nc = wn * 64 + nt * 8 + g;
                uint2 bhp = *(const uint2*)&pBh[nc * GWS + kb];
                #pragma unroll
                for (int mt = 0; mt < 2; mt++) {
                    mma_f16(acc[mt][nt], ah0[mt].x, ah1[mt].x, ah0[mt].y, ah1[mt].y, bhp.x, bhp.y);
                    mma_f16(acc[mt][nt], al0[mt].x, al1[mt].x, al0[mt].y, al1[mt].y, bhp.x, bhp.y);
                }
            }
        }
        __syncthreads();
    }
}

// ---------------------------------------------------------------------------
// merged Q/K/V projection: grid (18, 32). x<16: Q tile; x==16: K; x==17: V.
// ---------------------------------------------------------------------------
__global__ __launch_bounds__(256, 2)
void gemm_qkv(float* __restrict__ out, int M, int K)
{
    extern __shared__ unsigned dsm[];
    float acc[2][8][4];
    const int bm = blockIdx.y * BM;
    const int bx = blockIdx.x;

    const unsigned *Bhp;
    int bn;
    if (bx < 16)      { Bhp = g_wq_h; bn = bx * BN; }
    else if (bx == 16){ Bhp = g_wk_h; bn = 0; }
    else              { Bhp = g_wv_h; bn = 0; }

    gemm_core3(g_hs_hi, g_hs_lo, Bhp, K >> 1, bm, bn, dsm, acc);

    const int t = threadIdx.x, lane = t & 31, w = t >> 5;
    const int g = lane >> 2, tig = lane & 3;
    const int wm = w >> 1, wn = w & 1;

    if (bx < 16) {
        const int NW = HID >> 1;
        #pragma unroll
        for (int mt = 0; mt < 2; mt++) {
            int r0 = bm + wm * 32 + mt * 16 + g;
            #pragma unroll
            for (int nt = 0; nt < 8; nt++) {
                int wp = permw((bn >> 1) + wn * 32 + nt * 4 + tig);
                unsigned h0, l0;
                split2h(acc[mt][nt][0], acc[mt][nt][1], h0, l0);
                g_q_hi[(size_t)r0 * NW + wp] = h0;
                g_q_lo[(size_t)r0 * NW + wp] = l0;
                split2h(acc[mt][nt][2], acc[mt][nt][3], h0, l0);
                g_q_hi[(size_t)(r0 + 8) * NW + wp] = h0;
                g_q_lo[(size_t)(r0 + 8) * NW + wp] = l0;
            }
        }
        return;
    }

    const int NW = Dd >> 1;
    const size_t keybase = (size_t)MM * HID;
    const size_t valbase = keybase + (size_t)Bz * Hh * Sq * Dd;
    const size_t cachebase = (bx == 16) ? keybase : valbase;

    #pragma unroll
    for (int mt = 0; mt < 2; mt++) {
        int r0 = bm + wm * 32 + mt * 16 + g;
        #pragma unroll
        for (int nt = 0; nt < 8; nt++) {
            int c0 = wn * 64 + nt * 8 + tig * 2;
            float a0 = acc[mt][nt][0], a1 = acc[mt][nt][1];
            float a2 = acc[mt][nt][2], a3 = acc[mt][nt][3];

            #pragma unroll
            for (int rr = 0; rr < 2; rr++) {
                int r = r0 + rr * 8;
                int b = r >> 11;
                int s = r & (Sq - 1);
                float2 v2 = rr ? make_float2(a2, a3) : make_float2(a0, a1);
                size_t base = cachebase + ((size_t)b * Hh * Sq + s) * Dd + c0;
                #pragma unroll
                for (int h = 0; h < Hh; h++)
                    *(float2*)&out[base + (size_t)h * Sq * Dd] = v2;
            }

            if (bx == 16) {
                int wp = permw(c0 >> 1);
                g_k_h[(size_t)r0 * NW + wp]       = pack2h(a0, a1);
                g_k_h[(size_t)(r0 + 8) * NW + wp] = pack2h(a2, a3);
            } else {
                #pragma unroll
                for (int q = 0; q < 4; q++) {
                    float val = acc[mt][nt][q];
                    int cc = c0 + (q & 1);
                    int rr = r0 + (q >> 1) * 8;
                    int sp = permw(rr >> 1) * 2 + (rr & 1);
                    g_vT_h[(size_t)cc * MM + sp] = __float2half_rn(val);
                }
            }
        }
    }
}

// ---- O projection: fp32 output ---------------------------------------------
__global__ __launch_bounds__(256, 2)
void gemm_o2(float* __restrict__ C, int M, int N, int K)
{
    extern __shared__ unsigned dsm[];
    float acc[2][8][4];
    const int bm = blockIdx.y * BM, bn = blockIdx.x * BN;
    gemm_core3(g_a_hi, g_a_lo, g_wo_h, K >> 1, bm, bn, dsm, acc);

    const int t = threadIdx.x, lane = t & 31, w = t >> 5;
    const int g = lane >> 2, tig = lane & 3;
    const int wm = w >> 1, wn = w & 1;
    #pragma unroll
    for (int mt = 0; mt < 2; mt++) {
        int r0 = bm + wm * 32 + mt * 16 + g;
        #pragma unroll
        for (int nt = 0; nt < 8; nt++) {
            int c0 = bn + wn * 64 + nt * 8 + tig * 2;
            *(float2*)&C[(size_t)r0 * N + c0]       = make_float2(acc[mt][nt][0], acc[mt][nt][1]);
            *(float2*)&C[(size_t)(r0 + 8) * N + c0] = make_float2(acc[mt][nt][2], acc[mt][nt][3]);
        }
    }
}

// ---------------------------------------------------------------------------
// FlashAttention-2, 2xFP16 — 128 threads/CTA (4 warps), 64 q rows/CTA so two
// CTAs co-reside per SM (reg+smem fit) and overlap each other's stalls.
// Warp work is identical to R12 (16 rows x 64 keys, register softmax).
// ---------------------------------------------------------------------------
#define KROW 72
#define VROW 40
#define KBUF (64*KROW)     // 4608 words per stage (hi only)
#define VBUF (128*VROW)    // 5120 words per stage (hi only)
#define QBUF (64*KROW)     // Q staging (64 rows)
#define ATTN_SMEM_WORDS (2*KBUF + 2*VBUF + Sq)   // 21504 words = 86KB
#define NT_TILES (Sq/64)
#define ATHREADS 128

__global__ __launch_bounds__(ATHREADS)
void attn_kernel(const float* __restrict__ mask)
{
    extern __shared__ unsigned smw[];
    unsigned* Kh0 = smw;                    // 2 stages
    unsigned* Vh0 = smw + 2*KBUF;           // 2 stages
    float*  maskrow = (float*)(smw + 2*KBUF + 2*VBUF);

    const unsigned sbase = smem_u32(smw);

    const int t    = threadIdx.x;
    const int lane = t & 31, w = t >> 5;     // w in 0..3
    const int g    = lane >> 2, tig = lane & 3;
    const int qt   = blockIdx.x;             // 0..31 (64-row q tiles)
    const int bh   = blockIdx.y;
    const int b    = bh / Hh;
    const int h    = bh % Hh;
    const int m0   = w * 16;

    const float scale = 0.08838834764831845f;
    const float NEG   = -3.402823466e38f;

    #pragma unroll
    for (int i = 0; i < 4; i++) {
        int c = t + ATHREADS * i;            // 512 float4 chunks
        *(float4*)&maskrow[c * 4] = *(const float4*)&mask[b * Sq + c * 4];
    }

    // ---- stage Q (64 rows x 64 words): hi into K area, lo into V area ----
    #pragma unroll
    for (int i = 0; i < 8; i++) {
        int c = t + ATHREADS * i;            // 1024 chunks
        int r = c >> 4, cw = (c & 15) * 4;
        size_t goff = (size_t)(b * Sq + qt * 64 + r) * (HID/2) + h * (Dd/2) + cw;
        *(uint4*)&Kh0[r * KROW + cw] = *(const uint4*)&g_q_hi[goff];
        *(uint4*)&Vh0[r * KROW + cw] = *(const uint4*)&g_q_lo[goff];
    }
    __syncthreads();

    unsigned qh[8][4], ql[8][4];
    #pragma unroll
    for (int kf = 0; kf < 8; kf++) {
        int kb = kf * 8 + 2 * tig;
        uint2 p0 = *(const uint2*)&Kh0[(m0 + g    ) * KROW + kb];
        uint2 p1 = *(const uint2*)&Kh0[(m0 + g + 8) * KROW + kb];
        qh[kf][0] = p0.x; qh[kf][1] = p1.x; qh[kf][2] = p0.y; qh[kf][3] = p1.y;
        p0 = *(const uint2*)&Vh0[(m0 + g    ) * KROW + kb];
        p1 = *(const uint2*)&Vh0[(m0 + g + 8) * KROW + kb];
        ql[kf][0] = p0.x; ql[kf][1] = p1.x; ql[kf][2] = p0.y; ql[kf][3] = p1.y;
    }
    __syncthreads();

    float o[16][4];
    #pragma unroll
    for (int nd = 0; nd < 16; nd++)
        #pragma unroll
        for (int q = 0; q < 4; q++) o[nd][q] = 0.f;
    float mrow0 = -INFINITY, mrow1 = -INFINITY;
    float lsum0 = 0.f, lsum1 = 0.f;

    const unsigned* Vhw = (const unsigned*)g_vT_h;

    auto issue = [&](int kt, int bi) {
        unsigned dKh = sbase + (bi * KBUF) * 4;
        unsigned dVh = sbase + (2*KBUF + bi * VBUF) * 4;
        #pragma unroll
        for (int i = 0; i < 8; i++) {
            int c = t + ATHREADS * i;        // 1024 K chunks
            int r = c >> 4, cw = (c & 15) * 4;
            size_t goff = (size_t)(b * Sq + kt * 64 + r) * (Dd/2) + cw;
            cp16(dKh + (r * KROW + cw) * 4, &g_k_h[goff]);
        }
        #pragma unroll
        for (int i = 0; i < 8; i++) {
            int c = t + ATHREADS * i;        // 1024 V chunks
            int r = c >> 3, cw = (c & 7) * 4;
            size_t goff = (size_t)r * (MM/2) + (size_t)(b * Sq + kt * 64) / 2 + cw;
            cp16(dVh + (r * VROW + cw) * 4, &Vhw[goff]);
        }
    };

    issue(0, 0);
    cp_commit();

    for (int kt = 0; kt < NT_TILES; kt++) {
        const int bi = kt & 1;
        if (kt + 1 < NT_TILES) { issue(kt + 1, bi ^ 1); cp_commit(); cp_wait<1>(); }
        else                   { cp_wait<0>(); }
        __syncthreads();

        unsigned* Kh = Kh0 + bi * KBUF;
        unsigned* Vh = Vh0 + bi * VBUF;

        // ----- QK^T : hi-only B fragments, 2 mma each
        float s[8][4];
        #pragma unroll
        for (int nt = 0; nt < 8; nt++)
            #pragma unroll
            for (int q = 0; q < 4; q++) s[nt][q] = 0.f;

        #pragma unroll
        for (int kf = 0; kf < 8; kf++) {
            const int kb = kf * 8 + 2 * tig;
            #pragma unroll
            for (int nt = 0; nt < 8; nt++) {
                int nc = nt * 8 + g;
                uint2 bhp = *(const uint2*)&Kh[nc * KROW + kb];
                mma_f16(s[nt], qh[kf][0], qh[kf][1], qh[kf][2], qh[kf][3], bhp.x, bhp.y);
                mma_f16(s[nt], ql[kf][0], ql[kf][1], ql[kf][2], ql[kf][3], bhp.x, bhp.y);
            }
        }

        // ----- scale + mask + register softmax
        float m0new = -INFINITY, m1new = -INFINITY;
        #pragma unroll
        for (int nt = 0; nt < 8; nt++) {
            int c0 = kt * 64 + nt * 8 + tig * 2;
            float mt0 = (1.0f - maskrow[c0])     * NEG;
            float mt1 = (1.0f - maskrow[c0 + 1]) * NEG;
            s[nt][0] = s[nt][0] * scale + mt0;
            s[nt][1] = s[nt][1] * scale + mt1;
            s[nt][2] = s[nt][2] * scale + mt0;
            s[nt][3] = s[nt][3] * scale + mt1;
            m0new = fmaxf(m0new, fmaxf(s[nt][0], s[nt][1]));
            m1new = fmaxf(m1new, fmaxf(s[nt][2], s[nt][3]));
        }
        m0new = fmaxf(m0new, __shfl_xor_sync(0xffffffffu, m0new, 1));
        m0new = fmaxf(m0new, __shfl_xor_sync(0xffffffffu, m0new, 2));
        m1new = fmaxf(m1new, __shfl_xor_sync(0xffffffffu, m1new, 1));
        m1new = fmaxf(m1new, __shfl_xor_sync(0xffffffffu, m1new, 2));

        float newm0 = fmaxf(mrow0, m0new);
        float newm1 = fmaxf(mrow1, m1new);
        float corr0 = __expf(mrow0 - newm0);
        float corr1 = __expf(mrow1 - newm1);
        mrow0 = newm0; mrow1 = newm1;

        float ps0 = 0.f, ps1 = 0.f;
        #pragma unroll
        for (int nt = 0; nt < 8; nt++) {
            s[nt][0] = __expf(s[nt][0] - newm0);
            s[nt][1] = __expf(s[nt][1] - newm0);
            s[nt][2] = __expf(s[nt][2] - newm1);
            s[nt][3] = __expf(s[nt][3] - newm1);
            ps0 += s[nt][0] + s[nt][1];
            ps1 += s[nt][2] + s[nt][3];
        }
        ps0 += __shfl_xor_sync(0xffffffffu, ps0, 1);
        ps0 += __shfl_xor_sync(0xffffffffu, ps0, 2);
        ps1 += __shfl_xor_sync(0xffffffffu, ps1, 1);
        ps1 += __shfl_xor_sync(0xffffffffu, ps1, 2);
        lsum0 = lsum0 * corr0 + ps0;
        lsum1 = lsum1 * corr1 + ps1;

        #pragma unroll
        for (int nd = 0; nd < 16; nd++) {
            o[nd][0] *= corr0; o[nd][1] *= corr0;
            o[nd][2] *= corr1; o[nd][3] *= corr1;
        }

        // ----- PV : P split in regs (A-side), V hi-only, 2 mma each
        #pragma unroll
        for (int kf = 0; kf < 4; kf++) {
            unsigned a0h, a0l, a1h, a1l, a2h, a2l, a3h, a3l;
            split2h(s[2*kf  ][0], s[2*kf  ][1], a0h, a0l);
            split2h(s[2*kf  ][2], s[2*kf  ][3], a1h, a1l);
            split2h(s[2*kf+1][0], s[2*kf+1][1], a2h, a2l);
            split2h(s[2*kf+1][2], s[2*kf+1][3], a3h, a3l);
            const int kb = kf * 8 + 2 * tig;
            #pragma unroll
            for (int nd = 0; nd < 16; nd++) {
                int nc = nd * 8 + g;
                uint2 vhp = *(const uint2*)&Vh[nc * VROW + kb];
                mma_f16(o[nd], a0h, a1h, a2h, a3h, vhp.x, vhp.y);
                mma_f16(o[nd], a0l, a1l, a2l, a3l, vhp.x, vhp.y);
            }
        }
        __syncthreads();
    }

    // epilogue: normalize, split, permuted packed write
    float inv0 = 1.0f / lsum0;
    float inv1 = 1.0f / lsum1;
    size_t row0 = (size_t)(b * Sq + qt * 64 + m0 + g);
    #pragma unroll
    for (int nd = 0; nd < 16; nd++) {
        int cw = permw(h * (Dd/2) + nd * 4 + tig);
        unsigned hh, llw;
        split2h(o[nd][0] * inv0, o[nd][1] * inv0, hh, llw);
        g_a_hi[row0 * (HID/2) + cw] = hh;
        g_a_lo[row0 * (HID/2) + cw] = llw;
        split2h(o[nd][2] * inv1, o[nd][3] * inv1, hh, llw);
        g_a_hi[(row0 + 8) * (HID/2) + cw] = hh;
        g_a_lo[(row0 + 8) * (HID/2) + cw] = llw;
    }
}

// ---------------------------------------------------------------------------
extern "C" void kernel_launch(void* const* d_in, const int* in_sizes, int n_in,
                              void* d_out, int out_size)
{
    const float* hs   = (const float*)d_in[0];
    const float* mask = (const float*)d_in[1];
    const float* Wq   = (const float*)d_in[2];
    const float* Wk   = (const float*)d_in[3];
    const float* Wv   = (const float*)d_in[4];
    const float* Wo   = (const float*)d_in[5];
    float* out = (float*)d_out;

    void *hsh, *hsl;
    cudaGetSymbolAddress(&hsh, g_hs_hi);  cudaGetSymbolAddress(&hsl, g_hs_lo);

    cudaFuncSetAttribute(attn_kernel, cudaFuncAttributeMaxDynamicSharedMemorySize,
                         ATTN_SMEM_WORDS * 4);
    cudaFuncSetAttribute(gemm_qkv, cudaFuncAttributeMaxDynamicSharedMemorySize, GEMM_SMEM_BYTES);
    cudaFuncSetAttribute(gemm_o2,  cudaFuncAttributeMaxDynamicSharedMemorySize, GEMM_SMEM_BYTES);

    dim3 blk(256);
    // presplits: hs -> hi/lo, all four weights -> hi only (one launch)
    presplit_a<<<MM*HID/16/256, blk>>>(hs, (unsigned*)hsh, (unsigned*)hsl, MM*HID/16);
    presplit_w<<<dim3(HID*HID/16/256, 4), blk>>>(Wq, Wo, Wk, Wv);

    // merged Q/K/V projections (+ direct KV cache output writes)
    gemm_qkv<<<dim3(18, MM / BM), blk, GEMM_SMEM_BYTES>>>(out, MM, HID);
    // attention: 128-thread CTAs, 64 q-rows each -> 2 CTAs/SM
    attn_kernel<<<dim3(Sq / 64, Bz * Hh), dim3(ATHREADS), ATTN_SMEM_WORDS * 4>>>(mask);
    // output projection
    gemm_o2<<<dim3(HID / BN, MM / BM), blk, GEMM_SMEM_BYTES>>>(out, MM, HID, HID);
}